// round 4
// baseline (speedup 1.0000x reference)
#include <cuda_runtime.h>
#include <math.h>
#include <stdint.h>

#define BB 64
#define LC 1024
#define LQ 128
#define DD 128
#define NEG (-1e9f)

// ---------------- device scratch ----------------
__device__ float g_S[(size_t)BB * LC * LQ];      // finalized S, 32 MB
__device__ float g_rmax[BB * LC];
__device__ float g_rinv[BB * LC];
__device__ float g_cpm[BB * 16 * LQ];
__device__ float g_cps[BB * 16 * LQ];
__device__ float g_cmax[BB * LQ];
__device__ float g_cinv[BB * LQ];
__device__ float g_V2p[(size_t)4 * BB * LQ * DD];
__device__ float g_V2[BB * LQ * DD];

// ---------------- tf32 helpers ----------------
__device__ __forceinline__ float2 split2(float x) {
    uint32_t hi, lo;
    asm("cvt.rna.tf32.f32 %0, %1;" : "=r"(hi) : "f"(x));
    float r = x - __uint_as_float(hi);
    asm("cvt.rna.tf32.f32 %0, %1;" : "=r"(lo) : "f"(r));
    return make_float2(__uint_as_float(hi), __uint_as_float(lo));
}
__device__ __forceinline__ uint32_t fau(float x) { return __float_as_uint(x); }
__device__ __forceinline__ void mma8(float* d, const uint32_t* a, const uint32_t* b) {
    asm("mma.sync.aligned.m16n8k8.row.col.f32.tf32.tf32.f32 "
        "{%0,%1,%2,%3}, {%4,%5,%6,%7}, {%8,%9}, {%0,%1,%2,%3};"
        : "+f"(d[0]), "+f"(d[1]), "+f"(d[2]), "+f"(d[3])
        : "r"(a[0]), "r"(a[1]), "r"(a[2]), "r"(a[3]), "r"(b[0]), "r"(b[1]));
}
__device__ __forceinline__ void mma3(float* d, const uint32_t* ah, const uint32_t* al,
                                     const uint32_t* bh, const uint32_t* bl) {
    mma8(d, ah, bh);
    mma8(d, ah, bl);
    mma8(d, al, bh);
}

// ================= K1: S GEMM (3xTF32, pre-split) + dots + stats =========
// grid = BB*16, block 256 (8 warps = 4m x 2n). Tile: 64 i x 128 j.
// dyn smem: As2 float2[64][34] | Qs2 float2[128][34]; Ss float[64][132] alias.
#define S_DYN ((64 * 34 + 128 * 34) * (int)sizeof(float2))
__global__ __launch_bounds__(256, 2) void s_kernel(
    const float* __restrict__ Cg, const float* __restrict__ Qg,
    const float* __restrict__ w_mul, const float* __restrict__ w_c,
    const float* __restrict__ w_q, const float* __restrict__ bias,
    const int* __restrict__ Qmask, const int* __restrict__ Cmask) {
    extern __shared__ float2 dyn2[];
    float2* As2 = dyn2;              // [64][34]
    float2* Qs2 = dyn2 + 64 * 34;    // [128][34]
    float*  Ss  = (float*)dyn2;      // [64][132] epilogue alias
    __shared__ float s_cd[64], s_qd[128];
    __shared__ float s_m2[128], s_s2[128];
    __shared__ int s_qm[128], s_cm[64];

    int bx = blockIdx.x;
    int b = bx >> 4, tile = bx & 15, i0 = tile << 6;
    int t = threadIdx.x, wid = t >> 5, lane = t & 31;
    int g = lane >> 2, tg = lane & 3;
    int wm = wid & 3, wn = wid >> 2;
    int mb = wm << 4;          // 0..48
    int jb = wn << 6;          // 0 / 64

    if (t < 128) s_qm[t] = Qmask[b * LQ + t];
    if (t < 64)  s_cm[t] = Cmask[b * LC + i0 + t];

    float acc[8][4];
    #pragma unroll
    for (int nt = 0; nt < 8; nt++)
        #pragma unroll
        for (int e = 0; e < 4; e++) acc[nt][e] = 0.f;

    const float* Cb = Cg + ((size_t)b * LC + i0) * DD;
    const float* Qb = Qg + (size_t)b * LQ * DD;
    int li = t >> 2, lk = (t & 3) << 3;    // As loader: 8 elems
    int qj = t >> 1, qk = (t & 1) << 4;    // Qs loader: 16 elems
    float cdp = 0.f, qdp = 0.f;

    for (int kk = 0; kk < DD; kk += 32) {
        {   // As2 = split(C * w_mul) ; cdot partial
            const float* src = Cb + (size_t)li * DD + kk + lk;
            float4 v0 = *(const float4*)src;
            float4 v1 = *(const float4*)(src + 4);
            float4 m0 = *(const float4*)(w_mul + kk + lk);
            float4 m1 = *(const float4*)(w_mul + kk + lk + 4);
            float4 c0 = *(const float4*)(w_c + kk + lk);
            float4 c1 = *(const float4*)(w_c + kk + lk + 4);
            cdp += v0.x * c0.x + v0.y * c0.y + v0.z * c0.z + v0.w * c0.w
                 + v1.x * c1.x + v1.y * c1.y + v1.z * c1.z + v1.w * c1.w;
            float2* ar = As2 + li * 34 + lk;
            ar[0] = split2(v0.x * m0.x); ar[1] = split2(v0.y * m0.y);
            ar[2] = split2(v0.z * m0.z); ar[3] = split2(v0.w * m0.w);
            ar[4] = split2(v1.x * m1.x); ar[5] = split2(v1.y * m1.y);
            ar[6] = split2(v1.z * m1.z); ar[7] = split2(v1.w * m1.w);
        }
        {   // Qs2 = split(Q) ; qdot partial
            const float* src = Qb + (size_t)qj * DD + kk + qk;
            float2* qr = Qs2 + qj * 34 + qk;
            #pragma unroll
            for (int u = 0; u < 16; u += 4) {
                float4 v = *(const float4*)(src + u);
                float4 w = *(const float4*)(w_q + kk + qk + u);
                qdp += v.x * w.x + v.y * w.y + v.z * w.z + v.w * w.w;
                qr[u] = split2(v.x); qr[u + 1] = split2(v.y);
                qr[u + 2] = split2(v.z); qr[u + 3] = split2(v.w);
            }
        }
        __syncthreads();
        #pragma unroll
        for (int k8 = 0; k8 < 4; k8++) {
            int kb = k8 << 3;
            float2 a0 = As2[(mb + g) * 34 + kb + tg];
            float2 a1 = As2[(mb + g + 8) * 34 + kb + tg];
            float2 a2 = As2[(mb + g) * 34 + kb + tg + 4];
            float2 a3 = As2[(mb + g + 8) * 34 + kb + tg + 4];
            uint32_t ah[4] = {fau(a0.x), fau(a1.x), fau(a2.x), fau(a3.x)};
            uint32_t al[4] = {fau(a0.y), fau(a1.y), fau(a2.y), fau(a3.y)};
            #pragma unroll
            for (int nt = 0; nt < 8; nt++) {
                float2 b0 = Qs2[(jb + nt * 8 + g) * 34 + kb + tg];
                float2 b1 = Qs2[(jb + nt * 8 + g) * 34 + kb + tg + 4];
                uint32_t bh[2] = {fau(b0.x), fau(b1.x)};
                uint32_t bl[2] = {fau(b0.y), fau(b1.y)};
                mma3(acc[nt], ah, al, bh, bl);
            }
        }
        __syncthreads();
    }

    // reduce dots
    cdp += __shfl_xor_sync(0xffffffffu, cdp, 1);
    cdp += __shfl_xor_sync(0xffffffffu, cdp, 2);
    if ((t & 3) == 0) s_cd[li] = cdp;
    qdp += __shfl_xor_sync(0xffffffffu, qdp, 1);
    if ((t & 1) == 0) s_qd[qj] = qdp;
    __syncthreads();

    // finalize into Ss (overwrites As2/Qs2)
    {
        float bi = bias[0];
        float cd0 = s_cd[mb + g] + bi, cd1 = s_cd[mb + g + 8] + bi;
        #pragma unroll
        for (int nt = 0; nt < 8; nt++) {
            int c0 = jb + nt * 8 + 2 * tg;
            float q0 = s_qd[c0], q1 = s_qd[c0 + 1];
            Ss[(mb + g) * 132 + c0]     = acc[nt][0] + cd0 + q0;
            Ss[(mb + g) * 132 + c0 + 1] = acc[nt][1] + cd0 + q1;
            Ss[(mb + g + 8) * 132 + c0]     = acc[nt][2] + cd1 + q0;
            Ss[(mb + g + 8) * 132 + c0 + 1] = acc[nt][3] + cd1 + q1;
        }
    }
    __syncthreads();

    // phase A: row stats (qmask) + store g_S
    {
        int i = t >> 2, j0 = (t & 3) << 5;
        float mx = NEG;
        float* dst = g_S + ((size_t)(b * LC + i0 + i)) * LQ + j0;
        #pragma unroll
        for (int u = 0; u < 32; u += 4) {
            float4 v = *(const float4*)&Ss[i * 132 + j0 + u];
            int4 m = *(const int4*)&s_qm[j0 + u];
            *(float4*)(dst + u) = v;
            mx = fmaxf(mx, fmaxf(fmaxf(m.x ? v.x : NEG, m.y ? v.y : NEG),
                                 fmaxf(m.z ? v.z : NEG, m.w ? v.w : NEG)));
        }
        mx = fmaxf(mx, __shfl_xor_sync(0xffffffffu, mx, 1));
        mx = fmaxf(mx, __shfl_xor_sync(0xffffffffu, mx, 2));
        float sm = 0.f;
        #pragma unroll
        for (int u = 0; u < 32; u += 4) {
            float4 v = *(const float4*)&Ss[i * 132 + j0 + u];
            int4 m = *(const int4*)&s_qm[j0 + u];
            sm += __expf((m.x ? v.x : NEG) - mx) + __expf((m.y ? v.y : NEG) - mx)
                + __expf((m.z ? v.z : NEG) - mx) + __expf((m.w ? v.w : NEG) - mx);
        }
        sm += __shfl_xor_sync(0xffffffffu, sm, 1);
        sm += __shfl_xor_sync(0xffffffffu, sm, 2);
        if ((t & 3) == 0) {
            g_rmax[b * LC + i0 + i] = mx;
            g_rinv[b * LC + i0 + i] = 1.f / sm;
        }
    }

    // phase B: column partials (cmask) over this tile's 64 rows
    {
        int j = t & 127, ih = t >> 7;
        float m = NEG, s = 0.f;
        #pragma unroll 4
        for (int r = 0; r < 32; r++) {
            int i = ih * 32 + r;
            float v = s_cm[i] ? Ss[i * 132 + j] : NEG;
            float mn = fmaxf(m, v);
            s = s * __expf(m - mn) + __expf(v - mn);
            m = mn;
        }
        if (ih == 1) { s_m2[j] = m; s_s2[j] = s; }
        __syncthreads();
        if (ih == 0) {
            float m2 = s_m2[j], s2 = s_s2[j];
            float M = fmaxf(m, m2);
            float S = s * __expf(m - M) + s2 * __expf(m2 - M);
            g_cpm[(b * 16 + tile) * LQ + j] = M;
            g_cps[(b * 16 + tile) * LQ + j] = S;
        }
    }
}

// ================= K2: merge column partials =================
__global__ __launch_bounds__(256) void colmerge_kernel() {
    int idx = blockIdx.x * blockDim.x + threadIdx.x;
    if (idx >= BB * LQ) return;
    int b = idx >> 7, j = idx & 127;
    float M = NEG;
    #pragma unroll
    for (int g = 0; g < 16; g++) M = fmaxf(M, g_cpm[(b * 16 + g) * LQ + j]);
    float S = 0.f;
    #pragma unroll
    for (int g = 0; g < 16; g++) S += g_cps[(b * 16 + g) * LQ + j] * __expf(g_cpm[(b * 16 + g) * LQ + j] - M);
    g_cmax[idx] = M;
    g_cinv[idx] = 1.f / S;
}

// ================= K3: V2 partial (3xTF32, pre-split), split-K=4 =========
// grid = BB*4, block 256 (8 warps = 4m x 2n). M=128 j, N=128 d, K=256 i.
#define V2_DYN ((32 * 136 + 32 * 136) * (int)sizeof(float2))
__global__ __launch_bounds__(256, 2) void v2_kernel(
    const float* __restrict__ Cg, const int* __restrict__ Cmask) {
    extern __shared__ float2 dyn2[];
    float2* Ps2 = dyn2;              // [32][136] k-major [i'][j]
    float2* Cs2 = dyn2 + 32 * 136;   // [32][136] k-major [i'][d]
    __shared__ float s_cx[128], s_ci[128];
    __shared__ int s_cm[256];
    int b = blockIdx.x >> 2, gc = blockIdx.x & 3;
    int t = threadIdx.x, wid = t >> 5, lane = t & 31;
    int g = lane >> 2, tg = lane & 3;
    int wm = wid >> 1, wn = wid & 1;
    int mb0 = wm << 5;   // j base
    int nb = wn << 6;    // d base
    if (t < 128) {
        s_cx[t] = g_cmax[b * LQ + t];
        s_ci[t] = g_cinv[b * LQ + t];
    }
    s_cm[t] = Cmask[b * LC + gc * 256 + t];
    __syncthreads();

    float acc[2][8][4];
    #pragma unroll
    for (int mt = 0; mt < 2; mt++)
        #pragma unroll
        for (int nt = 0; nt < 8; nt++)
            #pragma unroll
            for (int e = 0; e < 4; e++) acc[mt][nt][e] = 0.f;

    int li = t >> 3, lj = (t & 7) << 4;
    for (int ik = 0; ik < 256; ik += 32) {
        {
            const float* srow = g_S + ((size_t)(b * LC + gc * 256 + ik + li)) * LQ + lj;
            int msk = s_cm[ik + li];
            float2* pr = Ps2 + li * 136 + lj;
            #pragma unroll
            for (int u = 0; u < 16; u += 4) {
                float4 v = *(const float4*)(srow + u);
                pr[u]     = split2(__expf((msk ? v.x : NEG) - s_cx[lj + u])     * s_ci[lj + u]);
                pr[u + 1] = split2(__expf((msk ? v.y : NEG) - s_cx[lj + u + 1]) * s_ci[lj + u + 1]);
                pr[u + 2] = split2(__expf((msk ? v.z : NEG) - s_cx[lj + u + 2]) * s_ci[lj + u + 2]);
                pr[u + 3] = split2(__expf((msk ? v.w : NEG) - s_cx[lj + u + 3]) * s_ci[lj + u + 3]);
            }
            const float* crow = Cg + ((size_t)(b * LC + gc * 256 + ik + li)) * DD + lj;
            float2* cr = Cs2 + li * 136 + lj;
            #pragma unroll
            for (int u = 0; u < 16; u += 4) {
                float4 v = *(const float4*)(crow + u);
                cr[u] = split2(v.x); cr[u + 1] = split2(v.y);
                cr[u + 2] = split2(v.z); cr[u + 3] = split2(v.w);
            }
        }
        __syncthreads();
        #pragma unroll
        for (int k8 = 0; k8 < 4; k8++) {
            int kb = k8 << 3;
            uint32_t ah[2][4], al[2][4];
            #pragma unroll
            for (int mt = 0; mt < 2; mt++) {
                int m0 = mb0 + mt * 16;
                float2 a0 = Ps2[(kb + tg) * 136 + m0 + g];
                float2 a1 = Ps2[(kb + tg) * 136 + m0 + g + 8];
                float2 a2 = Ps2[(kb + tg + 4) * 136 + m0 + g];
                float2 a3 = Ps2[(kb + tg + 4) * 136 + m0 + g + 8];
                ah[mt][0] = fau(a0.x); ah[mt][1] = fau(a1.x);
                ah[mt][2] = fau(a2.x); ah[mt][3] = fau(a3.x);
                al[mt][0] = fau(a0.y); al[mt][1] = fau(a1.y);
                al[mt][2] = fau(a2.y); al[mt][3] = fau(a3.y);
            }
            #pragma unroll
            for (int nt = 0; nt < 8; nt++) {
                float2 b0 = Cs2[(kb + tg) * 136 + nb + nt * 8 + g];
                float2 b1 = Cs2[(kb + tg + 4) * 136 + nb + nt * 8 + g];
                uint32_t bh[2] = {fau(b0.x), fau(b1.x)};
                uint32_t bl[2] = {fau(b0.y), fau(b1.y)};
                mma3(acc[0][nt], ah[0], al[0], bh, bl);
                mma3(acc[1][nt], ah[1], al[1], bh, bl);
            }
        }
        __syncthreads();
    }

    float* Vp = g_V2p + (size_t)(b * 4 + gc) * LQ * DD;
    #pragma unroll
    for (int mt = 0; mt < 2; mt++) {
        int r0 = mb0 + mt * 16 + g;
        #pragma unroll
        for (int nt = 0; nt < 8; nt++) {
            int d = nb + nt * 8 + 2 * tg;
            *(float2*)(Vp + (size_t)r0 * DD + d)       = make_float2(acc[mt][nt][0], acc[mt][nt][1]);
            *(float2*)(Vp + (size_t)(r0 + 8) * DD + d) = make_float2(acc[mt][nt][2], acc[mt][nt][3]);
        }
    }
}

__global__ __launch_bounds__(256) void v2reduce_kernel() {
    int vec = blockIdx.x * blockDim.x + threadIdx.x;
    const int per_b = LQ * DD / 4;
    if (vec >= BB * per_b) return;
    int b = vec / per_b;
    int off = vec % per_b;
    float4 s = make_float4(0.f, 0.f, 0.f, 0.f);
    #pragma unroll
    for (int g = 0; g < 4; g++) {
        float4 v = ((const float4*)(g_V2p + (size_t)(b * 4 + g) * LQ * DD))[off];
        s.x += v.x; s.y += v.y; s.z += v.z; s.w += v.w;
    }
    ((float4*)g_V2)[vec] = s;
}

// ================= K4: A = P1@Q, Bm = P1@V2 (3xTF32, pre-split) ==========
// grid = BB*16, block 256 (8 warps = 4m x 2n). Tile 64 i x 128 n.
#define F_DYN ((64 * 130 + 16 * 136) * (int)sizeof(float2))
__global__ __launch_bounds__(256, 2) void final_kernel(
    const float* __restrict__ Cg, const float* __restrict__ Qg,
    const int* __restrict__ Qmask, float* __restrict__ out) {
    extern __shared__ float2 dyn2[];
    float2* Ps2 = dyn2;              // [64][130] m-major [i][j], full K
    float2* Bs2 = dyn2 + 64 * 130;   // [16][136] k-major [j'][d]
    int bx = blockIdx.x;
    int b = bx >> 4, i0 = (bx & 15) << 6;
    int t = threadIdx.x, wid = t >> 5, lane = t & 31;
    int g = lane >> 2, tg = lane & 3;
    int wm = wid & 3, wn = wid >> 2;
    int mb = wm << 4, nb = wn << 6;

    {   // build P1 tile, pre-split
        int i = t >> 2, j0 = (t & 3) << 5;
        int gi = b * LC + i0 + i;
        float rm = __ldg(&g_rmax[gi]), ri = __ldg(&g_rinv[gi]);
        const float* srow = g_S + (size_t)gi * LQ + j0;
        const int* qm = Qmask + b * LQ + j0;
        float2* pr = Ps2 + i * 130 + j0;
        #pragma unroll
        for (int u = 0; u < 32; u += 4) {
            float4 v = *(const float4*)(srow + u);
            int4 m = *(const int4*)(qm + u);
            pr[u]     = split2(__expf((m.x ? v.x : NEG) - rm) * ri);
            pr[u + 1] = split2(__expf((m.y ? v.y : NEG) - rm) * ri);
            pr[u + 2] = split2(__expf((m.z ? v.z : NEG) - rm) * ri);
            pr[u + 3] = split2(__expf((m.w ? v.w : NEG) - rm) * ri);
        }
    }
    __syncthreads();

    int lk = t >> 4, ld0 = (t & 15) << 3;
    #pragma unroll
    for (int pass = 0; pass < 2; pass++) {
        const float* Bsrc = pass ? (g_V2 + (size_t)b * LQ * DD) : (Qg + (size_t)b * LQ * DD);
        float acc[8][4];
        #pragma unroll
        for (int nt = 0; nt < 8; nt++)
            #pragma unroll
            for (int e = 0; e < 4; e++) acc[nt][e] = 0.f;

        for (int kk = 0; kk < LQ; kk += 16) {
            {
                const float* br = Bsrc + (size_t)(kk + lk) * DD + ld0;
                float4 v0 = *(const float4*)br;
                float4 v1 = *(const float4*)(br + 4);
                float2* bd = Bs2 + lk * 136 + ld0;
                bd[0] = split2(v0.x); bd[1] = split2(v0.y);
                bd[2] = split2(v0.z); bd[3] = split2(v0.w);
                bd[4] = split2(v1.x); bd[5] = split2(v1.y);
                bd[6] = split2(v1.z); bd[7] = split2(v1.w);
            }
            __syncthreads();
            #pragma unroll
            for (int k8 = 0; k8 < 2; k8++) {
                int kb = k8 << 3;
                float2 a0 = Ps2[(mb + g) * 130 + kk + kb + tg];
                float2 a1 = Ps2[(mb + g + 8) * 130 + kk + kb + tg];
                float2 a2 = Ps2[(mb + g) * 130 + kk + kb + tg + 4];
                float2 a3 = Ps2[(mb + g + 8) * 130 + kk + kb + tg + 4];
                uint32_t ah[4] = {fau(a0.x), fau(a1.x), fau(a2.x), fau(a3.x)};
                uint32_t al[4] = {fau(a0.y), fau(a1.y), fau(a2.y), fau(a3.y)};
                #pragma unroll
                for (int nt = 0; nt < 8; nt++) {
                    float2 b0 = Bs2[(kb + tg) * 136 + nb + nt * 8 + g];
                    float2 b1 = Bs2[(kb + tg + 4) * 136 + nb + nt * 8 + g];
                    uint32_t bh[2] = {fau(b0.x), fau(b1.x)};
                    uint32_t bl[2] = {fau(b0.y), fau(b1.y)};
                    mma3(acc[nt], ah, al, bh, bl);
                }
            }
            __syncthreads();
        }

        // epilogue
        int r0 = i0 + mb + g, r1 = r0 + 8;
        const float* c0p = Cg + ((size_t)(b * LC + r0)) * DD;
        const float* c1p = Cg + ((size_t)(b * LC + r1)) * DD;
        float* o0 = out + ((size_t)(b * LC + r0)) * (4 * DD);
        float* o1 = out + ((size_t)(b * LC + r1)) * (4 * DD);
        #pragma unroll
        for (int nt = 0; nt < 8; nt++) {
            int d = nb + nt * 8 + 2 * tg;
            float2 c0 = *(const float2*)(c0p + d);
            float2 c1 = *(const float2*)(c1p + d);
            if (pass == 0) {
                *(float2*)(o0 + d) = c0;
                *(float2*)(o1 + d) = c1;
                *(float2*)(o0 + DD + d) = make_float2(acc[nt][0], acc[nt][1]);
                *(float2*)(o1 + DD + d) = make_float2(acc[nt][2], acc[nt][3]);
                *(float2*)(o0 + 2 * DD + d) = make_float2(c0.x * acc[nt][0], c0.y * acc[nt][1]);
                *(float2*)(o1 + 2 * DD + d) = make_float2(c1.x * acc[nt][2], c1.y * acc[nt][3]);
            } else {
                *(float2*)(o0 + 3 * DD + d) = make_float2(c0.x * acc[nt][0], c0.y * acc[nt][1]);
                *(float2*)(o1 + 3 * DD + d) = make_float2(c1.x * acc[nt][2], c1.y * acc[nt][3]);
            }
        }
    }
}

// ---------------- launch ----------------
extern "C" void kernel_launch(void* const* d_in, const int* in_sizes, int n_in,
                              void* d_out, int out_size) {
    const float* C     = (const float*)d_in[0];
    const float* Q     = (const float*)d_in[1];
    const int*   Cmask = (const int*)d_in[2];
    const int*   Qmask = (const int*)d_in[3];
    const float* w_c   = (const float*)d_in[4];
    const float* w_q   = (const float*)d_in[5];
    const float* w_mul = (const float*)d_in[6];
    const float* bias  = (const float*)d_in[7];
    float* out = (float*)d_out;

    static int attr_done = 0;
    if (!attr_done) {
        cudaFuncSetAttribute(s_kernel, cudaFuncAttributeMaxDynamicSharedMemorySize, S_DYN);
        cudaFuncSetAttribute(v2_kernel, cudaFuncAttributeMaxDynamicSharedMemorySize, V2_DYN);
        cudaFuncSetAttribute(final_kernel, cudaFuncAttributeMaxDynamicSharedMemorySize, F_DYN);
        attr_done = 1;
    }

    s_kernel<<<BB * 16, 256, S_DYN>>>(C, Q, w_mul, w_c, w_q, bias, Qmask, Cmask);
    colmerge_kernel<<<(BB * LQ + 255) / 256, 256>>>();
    v2_kernel<<<BB * 4, 256, V2_DYN>>>(C, Cmask);
    v2reduce_kernel<<<(BB * LQ * DD / 4 + 255) / 256, 256>>>();
    final_kernel<<<BB * 16, 256, F_DYN>>>(C, Q, Qmask, out);
}

// round 6
// speedup vs baseline: 1.3601x; 1.3601x over previous
#include <cuda_runtime.h>
#include <math.h>
#include <stdint.h>

#define BB 64
#define LC 1024
#define LQ 128
#define DD 128
#define NEG (-1e9f)

// ---------------- device scratch ----------------
__device__ float g_S[(size_t)BB * LC * LQ];      // finalized S, 32 MB
__device__ float g_rmax[BB * LC];
__device__ float g_rinv[BB * LC];
__device__ float g_cpm[BB * 8 * LQ];             // 8 chunks of 128 rows
__device__ float g_cps[BB * 8 * LQ];
__device__ float g_cmax[BB * LQ];
__device__ float g_cinv[BB * LQ];
__device__ float g_V2p[(size_t)8 * BB * LQ * DD];
__device__ float g_V2[BB * LQ * DD];

// ---------------- tf32 mma helpers ----------------
__device__ __forceinline__ void split_tf32(float x, uint32_t& hi, uint32_t& lo) {
    asm("cvt.rna.tf32.f32 %0, %1;" : "=r"(hi) : "f"(x));
    float r = x - __uint_as_float(hi);
    asm("cvt.rna.tf32.f32 %0, %1;" : "=r"(lo) : "f"(r));
}
__device__ __forceinline__ void mma8(float* d, const uint32_t* a, const uint32_t* b) {
    asm("mma.sync.aligned.m16n8k8.row.col.f32.tf32.tf32.f32 "
        "{%0,%1,%2,%3}, {%4,%5,%6,%7}, {%8,%9}, {%0,%1,%2,%3};"
        : "+f"(d[0]), "+f"(d[1]), "+f"(d[2]), "+f"(d[3])
        : "r"(a[0]), "r"(a[1]), "r"(a[2]), "r"(a[3]), "r"(b[0]), "r"(b[1]));
}
__device__ __forceinline__ void mma3(float* d, const uint32_t* ah, const uint32_t* al,
                                     const uint32_t* bh, const uint32_t* bl) {
    mma8(d, ah, bh);
    mma8(d, ah, bl);
    mma8(d, al, bh);
}

// ================= K1: S GEMM (3xTF32) + dots + stats =================
// grid = BB*8, block 256 (8 warps = 4m x 2n, warp m32n64 via mt=2).
// Tile: 128 i x 128 j. dyn smem union: {As f32[128][36], Qs f32[128][36]} / Ss f32[128][132]
#define S_DYN (128 * 132 * 4)
__global__ __launch_bounds__(256, 2) void s_kernel(
    const float* __restrict__ Cg, const float* __restrict__ Qg,
    const float* __restrict__ w_mul, const float* __restrict__ w_c,
    const float* __restrict__ w_q, const float* __restrict__ bias,
    const int* __restrict__ Qmask, const int* __restrict__ Cmask) {
    extern __shared__ float dynf[];
    float* As = dynf;                // [128][36]
    float* Qs = dynf + 128 * 36;     // [128][36]
    float* Ss = dynf;                // [128][132] epilogue alias
    __shared__ float s_cd[128], s_qd[128];
    __shared__ float s_m2[128], s_s2[128];
    __shared__ int s_qm[128], s_cm[128];

    int bx = blockIdx.x;
    int b = bx >> 3, tile = bx & 7, i0 = tile << 7;
    int t = threadIdx.x, wid = t >> 5, lane = t & 31;
    int g = lane >> 2, tg = lane & 3;
    int wm = wid & 3, wn = wid >> 2;
    int mb = wm << 5;          // 0,32,64,96
    int jb = wn << 6;          // 0 / 64

    if (t < 128) {
        s_qm[t] = Qmask[b * LQ + t];
        s_cm[t] = Cmask[b * LC + i0 + t];
    }

    float acc[2][8][4];
    #pragma unroll
    for (int mt = 0; mt < 2; mt++)
        #pragma unroll
        for (int nt = 0; nt < 8; nt++)
            #pragma unroll
            for (int e = 0; e < 4; e++) acc[mt][nt][e] = 0.f;

    const float* Cb = Cg + ((size_t)b * LC + i0) * DD;
    const float* Qb = Qg + (size_t)b * LQ * DD;
    int li = t >> 1, lk = (t & 1) << 4;    // loaders: 16 elems each
    float cdp = 0.f, qdp = 0.f;

    for (int kk = 0; kk < DD; kk += 32) {
        {   // As = C * w_mul ; cdot partial
            const float* src = Cb + (size_t)li * DD + kk + lk;
            float* ar = As + li * 36 + lk;
            #pragma unroll
            for (int u = 0; u < 16; u += 4) {
                float4 v = *(const float4*)(src + u);
                float4 m = *(const float4*)(w_mul + kk + lk + u);
                float4 c = *(const float4*)(w_c + kk + lk + u);
                cdp += v.x * c.x + v.y * c.y + v.z * c.z + v.w * c.w;
                ar[u] = v.x * m.x; ar[u + 1] = v.y * m.y;
                ar[u + 2] = v.z * m.z; ar[u + 3] = v.w * m.w;
            }
        }
        {   // Qs ; qdot partial
            const float* src = Qb + (size_t)li * DD + kk + lk;
            float* qr = Qs + li * 36 + lk;
            #pragma unroll
            for (int u = 0; u < 16; u += 4) {
                float4 v = *(const float4*)(src + u);
                float4 w = *(const float4*)(w_q + kk + lk + u);
                qdp += v.x * w.x + v.y * w.y + v.z * w.z + v.w * w.w;
                qr[u] = v.x; qr[u + 1] = v.y; qr[u + 2] = v.z; qr[u + 3] = v.w;
            }
        }
        __syncthreads();
        #pragma unroll
        for (int k8 = 0; k8 < 4; k8++) {
            int kb = k8 << 3;
            uint32_t ah[2][4], al[2][4];
            #pragma unroll
            for (int mt = 0; mt < 2; mt++) {
                int m0 = mb + mt * 16;
                split_tf32(As[(m0 + g) * 36 + kb + tg],         ah[mt][0], al[mt][0]);
                split_tf32(As[(m0 + g + 8) * 36 + kb + tg],     ah[mt][1], al[mt][1]);
                split_tf32(As[(m0 + g) * 36 + kb + tg + 4],     ah[mt][2], al[mt][2]);
                split_tf32(As[(m0 + g + 8) * 36 + kb + tg + 4], ah[mt][3], al[mt][3]);
            }
            #pragma unroll
            for (int nt = 0; nt < 8; nt++) {
                uint32_t bh[2], bl[2];
                split_tf32(Qs[(jb + nt * 8 + g) * 36 + kb + tg],     bh[0], bl[0]);
                split_tf32(Qs[(jb + nt * 8 + g) * 36 + kb + tg + 4], bh[1], bl[1]);
                mma3(acc[0][nt], ah[0], al[0], bh, bl);
                mma3(acc[1][nt], ah[1], al[1], bh, bl);
            }
        }
        __syncthreads();
    }

    // reduce dots (pairs share a row)
    cdp += __shfl_xor_sync(0xffffffffu, cdp, 1);
    if ((t & 1) == 0) s_cd[li] = cdp;
    qdp += __shfl_xor_sync(0xffffffffu, qdp, 1);
    if ((t & 1) == 0) s_qd[li] = qdp;
    __syncthreads();

    // finalize into Ss (overwrites As/Qs)
    {
        float bi = bias[0];
        #pragma unroll
        for (int mt = 0; mt < 2; mt++) {
            int m0 = mb + mt * 16;
            float cd0 = s_cd[m0 + g] + bi, cd1 = s_cd[m0 + g + 8] + bi;
            #pragma unroll
            for (int nt = 0; nt < 8; nt++) {
                int c0 = jb + nt * 8 + 2 * tg;
                float q0 = s_qd[c0], q1 = s_qd[c0 + 1];
                Ss[(m0 + g) * 132 + c0]     = acc[mt][nt][0] + cd0 + q0;
                Ss[(m0 + g) * 132 + c0 + 1] = acc[mt][nt][1] + cd0 + q1;
                Ss[(m0 + g + 8) * 132 + c0]     = acc[mt][nt][2] + cd1 + q0;
                Ss[(m0 + g + 8) * 132 + c0 + 1] = acc[mt][nt][3] + cd1 + q1;
            }
        }
    }
    __syncthreads();

    // phase A: row stats (qmask) + store g_S. 2 threads per row, 64 j each.
    {
        int i = t >> 1, j0 = (t & 1) << 6;
        float mx = NEG;
        float* dst = g_S + ((size_t)(b * LC + i0 + i)) * LQ + j0;
        #pragma unroll
        for (int u = 0; u < 64; u += 4) {
            float4 v = *(const float4*)&Ss[i * 132 + j0 + u];
            int4 m = *(const int4*)&s_qm[j0 + u];
            *(float4*)(dst + u) = v;
            mx = fmaxf(mx, fmaxf(fmaxf(m.x ? v.x : NEG, m.y ? v.y : NEG),
                                 fmaxf(m.z ? v.z : NEG, m.w ? v.w : NEG)));
        }
        mx = fmaxf(mx, __shfl_xor_sync(0xffffffffu, mx, 1));
        float sm = 0.f;
        #pragma unroll
        for (int u = 0; u < 64; u += 4) {
            float4 v = *(const float4*)&Ss[i * 132 + j0 + u];
            int4 m = *(const int4*)&s_qm[j0 + u];
            sm += __expf((m.x ? v.x : NEG) - mx) + __expf((m.y ? v.y : NEG) - mx)
                + __expf((m.z ? v.z : NEG) - mx) + __expf((m.w ? v.w : NEG) - mx);
        }
        sm += __shfl_xor_sync(0xffffffffu, sm, 1);
        if ((t & 1) == 0) {
            g_rmax[b * LC + i0 + i] = mx;
            g_rinv[b * LC + i0 + i] = 1.f / sm;
        }
    }

    // phase B: column partials (cmask) over this tile's 128 rows
    {
        int j = t & 127, ih = t >> 7;
        float m = NEG, s = 0.f;
        #pragma unroll 4
        for (int r = 0; r < 64; r++) {
            int i = ih * 64 + r;
            float v = s_cm[i] ? Ss[i * 132 + j] : NEG;
            float mn = fmaxf(m, v);
            s = s * __expf(m - mn) + __expf(v - mn);
            m = mn;
        }
        if (ih == 1) { s_m2[j] = m; s_s2[j] = s; }
        __syncthreads();
        if (ih == 0) {
            float m2 = s_m2[j], s2 = s_s2[j];
            float M = fmaxf(m, m2);
            float S = s * __expf(m - M) + s2 * __expf(m2 - M);
            g_cpm[(b * 8 + tile) * LQ + j] = M;
            g_cps[(b * 8 + tile) * LQ + j] = S;
        }
    }
}

// ================= K2: merge column partials =================
__global__ __launch_bounds__(256) void colmerge_kernel() {
    int idx = blockIdx.x * blockDim.x + threadIdx.x;
    if (idx >= BB * LQ) return;
    int b = idx >> 7, j = idx & 127;
    float M = NEG;
    #pragma unroll
    for (int g = 0; g < 8; g++) M = fmaxf(M, g_cpm[(b * 8 + g) * LQ + j]);
    float S = 0.f;
    #pragma unroll
    for (int g = 0; g < 8; g++) S += g_cps[(b * 8 + g) * LQ + j] * __expf(g_cpm[(b * 8 + g) * LQ + j] - M);
    g_cmax[idx] = M;
    g_cinv[idx] = 1.f / S;
}

// ================= K3: V2 partial = P2^T(chunk) @ C(chunk), 3xTF32 =====
// grid = BB*8, block 256 (8 warps = 4m x 2n, warp m32n64). K=128 per chunk.
__global__ __launch_bounds__(256, 2) void v2_kernel(
    const float* __restrict__ Cg, const int* __restrict__ Cmask) {
    __shared__ float Ps[32 * 136];   // k-major: [i'][j]
    __shared__ float Cs[32 * 136];   // k-major: [i'][d]
    __shared__ float s_cx[128], s_ci[128];
    __shared__ int s_cm[128];
    int b = blockIdx.x >> 3, gc = blockIdx.x & 7;
    int t = threadIdx.x, wid = t >> 5, lane = t & 31;
    int g = lane >> 2, tg = lane & 3;
    int wm = wid >> 1, wn = wid & 1;
    int mb0 = wm << 5;   // j base
    int nb = wn << 6;    // d base
    if (t < 128) {
        s_cx[t] = g_cmax[b * LQ + t];
        s_ci[t] = g_cinv[b * LQ + t];
        s_cm[t] = Cmask[b * LC + gc * 128 + t];
    }
    __syncthreads();

    float acc[2][8][4];
    #pragma unroll
    for (int mt = 0; mt < 2; mt++)
        #pragma unroll
        for (int nt = 0; nt < 8; nt++)
            #pragma unroll
            for (int e = 0; e < 4; e++) acc[mt][nt][e] = 0.f;

    int li = t >> 3, lj = (t & 7) << 4;
    for (int ik = 0; ik < 128; ik += 32) {
        {
            const float* srow = g_S + ((size_t)(b * LC + gc * 128 + ik + li)) * LQ + lj;
            int msk = s_cm[ik + li];
            float* pr = Ps + li * 136 + lj;
            #pragma unroll
            for (int u = 0; u < 16; u += 4) {
                float4 v = *(const float4*)(srow + u);
                pr[u]     = __expf((msk ? v.x : NEG) - s_cx[lj + u])     * s_ci[lj + u];
                pr[u + 1] = __expf((msk ? v.y : NEG) - s_cx[lj + u + 1]) * s_ci[lj + u + 1];
                pr[u + 2] = __expf((msk ? v.z : NEG) - s_cx[lj + u + 2]) * s_ci[lj + u + 2];
                pr[u + 3] = __expf((msk ? v.w : NEG) - s_cx[lj + u + 3]) * s_ci[lj + u + 3];
            }
            const float* crow = Cg + ((size_t)(b * LC + gc * 128 + ik + li)) * DD + lj;
            float* cr = Cs + li * 136 + lj;
            #pragma unroll
            for (int u = 0; u < 16; u += 4) {
                float4 v = *(const float4*)(crow + u);
                cr[u] = v.x; cr[u + 1] = v.y; cr[u + 2] = v.z; cr[u + 3] = v.w;
            }
        }
        __syncthreads();
        #pragma unroll
        for (int k8 = 0; k8 < 4; k8++) {
            int kb = k8 << 3;
            uint32_t ah[2][4], al[2][4];
            #pragma unroll
            for (int mt = 0; mt < 2; mt++) {
                int m0 = mb0 + mt * 16;
                split_tf32(Ps[(kb + tg) * 136 + m0 + g],         ah[mt][0], al[mt][0]);
                split_tf32(Ps[(kb + tg) * 136 + m0 + g + 8],     ah[mt][1], al[mt][1]);
                split_tf32(Ps[(kb + tg + 4) * 136 + m0 + g],     ah[mt][2], al[mt][2]);
                split_tf32(Ps[(kb + tg + 4) * 136 + m0 + g + 8], ah[mt][3], al[mt][3]);
            }
            #pragma unroll
            for (int nt = 0; nt < 8; nt++) {
                uint32_t bh[2], bl[2];
                split_tf32(Cs[(kb + tg) * 136 + nb + nt * 8 + g],     bh[0], bl[0]);
                split_tf32(Cs[(kb + tg + 4) * 136 + nb + nt * 8 + g], bh[1], bl[1]);
                mma3(acc[0][nt], ah[0], al[0], bh, bl);
                mma3(acc[1][nt], ah[1], al[1], bh, bl);
            }
        }
        __syncthreads();
    }

    float* Vp = g_V2p + (size_t)(b * 8 + gc) * LQ * DD;
    #pragma unroll
    for (int mt = 0; mt < 2; mt++) {
        int r0 = mb0 + mt * 16 + g;
        #pragma unroll
        for (int nt = 0; nt < 8; nt++) {
            int d = nb + nt * 8 + 2 * tg;
            *(float2*)(Vp + (size_t)r0 * DD + d)       = make_float2(acc[mt][nt][0], acc[mt][nt][1]);
            *(float2*)(Vp + (size_t)(r0 + 8) * DD + d) = make_float2(acc[mt][nt][2], acc[mt][nt][3]);
        }
    }
}

__global__ __launch_bounds__(256) void v2reduce_kernel() {
    int vec = blockIdx.x * blockDim.x + threadIdx.x;
    const int per_b = LQ * DD / 4;
    if (vec >= BB * per_b) return;
    int b = vec / per_b;
    int off = vec % per_b;
    float4 s = make_float4(0.f, 0.f, 0.f, 0.f);
    #pragma unroll
    for (int g = 0; g < 8; g++) {
        float4 v = ((const float4*)(g_V2p + (size_t)(b * 8 + g) * LQ * DD))[off];
        s.x += v.x; s.y += v.y; s.z += v.z; s.w += v.w;
    }
    ((float4*)g_V2)[vec] = s;
}

// ================= K4: A = P1@Q, Bm = P1@V2 (3xTF32) =====================
// grid = BB*8, block 256 (8 warps = 4m x 2n, warp m32n64). Tile 128 i x 128 n.
#define F_DYN ((128 * 130 + 16 * 136) * 4)
__global__ __launch_bounds__(256, 2) void final_kernel(
    const float* __restrict__ Cg, const float* __restrict__ Qg,
    const int* __restrict__ Qmask, float* __restrict__ out) {
    extern __shared__ float dynf[];
    float* Ps = dynf;                // [128][130] m-major [i][j], full K
    float* Bs = dynf + 128 * 130;    // [16][136] k-major chunk [j'][d]
    int bx = blockIdx.x;
    int b = bx >> 3, i0 = (bx & 7) << 7;
    int t = threadIdx.x, wid = t >> 5, lane = t & 31;
    int g = lane >> 2, tg = lane & 3;
    int wm = wid & 3, wn = wid >> 2;
    int mb = wm << 5, nb = wn << 6;

    {   // build P1 tile: 2 threads per row, 64 j each
        int i = t >> 1, j0 = (t & 1) << 6;
        int gi = b * LC + i0 + i;
        float rm = __ldg(&g_rmax[gi]), ri = __ldg(&g_rinv[gi]);
        const float* srow = g_S + (size_t)gi * LQ + j0;
        const int* qm = Qmask + b * LQ + j0;
        float* pr = Ps + i * 130 + j0;
        #pragma unroll
        for (int u = 0; u < 64; u += 4) {
            float4 v = *(const float4*)(srow + u);
            int4 m = *(const int4*)(qm + u);
            pr[u]     = __expf((m.x ? v.x : NEG) - rm) * ri;
            pr[u + 1] = __expf((m.y ? v.y : NEG) - rm) * ri;
            pr[u + 2] = __expf((m.z ? v.z : NEG) - rm) * ri;
            pr[u + 3] = __expf((m.w ? v.w : NEG) - rm) * ri;
        }
    }
    __syncthreads();

    int lk = t >> 4, ld0 = (t & 15) << 3;
    #pragma unroll
    for (int pass = 0; pass < 2; pass++) {
        const float* Bsrc = pass ? (g_V2 + (size_t)b * LQ * DD) : (Qg + (size_t)b * LQ * DD);
        float acc[2][8][4];
        #pragma unroll
        for (int mt = 0; mt < 2; mt++)
            #pragma unroll
            for (int nt = 0; nt < 8; nt++)
                #pragma unroll
                for (int e = 0; e < 4; e++) acc[mt][nt][e] = 0.f;

        for (int kk = 0; kk < LQ; kk += 16) {
            {
                const float* br = Bsrc + (size_t)(kk + lk) * DD + ld0;
                float4 v0 = *(const float4*)br;
                float4 v1 = *(const float4*)(br + 4);
                float* bd = Bs + lk * 136 + ld0;
                bd[0] = v0.x; bd[1] = v0.y; bd[2] = v0.z; bd[3] = v0.w;
                bd[4] = v1.x; bd[5] = v1.y; bd[6] = v1.z; bd[7] = v1.w;
            }
            __syncthreads();
            #pragma unroll
            for (int k8 = 0; k8 < 2; k8++) {
                int kb = k8 << 3;
                uint32_t ah[2][4], al[2][4];
                #pragma unroll
                for (int mt = 0; mt < 2; mt++) {
                    int m0 = mb + mt * 16;
                    split_tf32(Ps[(m0 + g) * 130 + kk + kb + tg],         ah[mt][0], al[mt][0]);
                    split_tf32(Ps[(m0 + g + 8) * 130 + kk + kb + tg],     ah[mt][1], al[mt][1]);
                    split_tf32(Ps[(m0 + g) * 130 + kk + kb + tg + 4],     ah[mt][2], al[mt][2]);
                    split_tf32(Ps[(m0 + g + 8) * 130 + kk + kb + tg + 4], ah[mt][3], al[mt][3]);
                }
                #pragma unroll
                for (int nt = 0; nt < 8; nt++) {
                    uint32_t bh[2], bl[2];
                    split_tf32(Bs[(kb + tg) * 136 + nb + nt * 8 + g],     bh[0], bl[0]);
                    split_tf32(Bs[(kb + tg + 4) * 136 + nb + nt * 8 + g], bh[1], bl[1]);
                    mma3(acc[0][nt], ah[0], al[0], bh, bl);
                    mma3(acc[1][nt], ah[1], al[1], bh, bl);
                }
            }
            __syncthreads();
        }

        // epilogue
        #pragma unroll
        for (int mt = 0; mt < 2; mt++) {
            int r0 = i0 + mb + mt * 16 + g, r1 = r0 + 8;
            const float* c0p = Cg + ((size_t)(b * LC + r0)) * DD;
            const float* c1p = Cg + ((size_t)(b * LC + r1)) * DD;
            float* o0 = out + ((size_t)(b * LC + r0)) * (4 * DD);
            float* o1 = out + ((size_t)(b * LC + r1)) * (4 * DD);
            #pragma unroll
            for (int nt = 0; nt < 8; nt++) {
                int d = nb + nt * 8 + 2 * tg;
                float2 c0 = *(const float2*)(c0p + d);
                float2 c1 = *(const float2*)(c1p + d);
                float* a = acc[mt][nt];
                if (pass == 0) {
                    *(float2*)(o0 + d) = c0;
                    *(float2*)(o1 + d) = c1;
                    *(float2*)(o0 + DD + d) = make_float2(a[0], a[1]);
                    *(float2*)(o1 + DD + d) = make_float2(a[2], a[3]);
                    *(float2*)(o0 + 2 * DD + d) = make_float2(c0.x * a[0], c0.y * a[1]);
                    *(float2*)(o1 + 2 * DD + d) = make_float2(c1.x * a[2], c1.y * a[3]);
                } else {
                    *(float2*)(o0 + 3 * DD + d) = make_float2(c0.x * a[0], c0.y * a[1]);
                    *(float2*)(o1 + 3 * DD + d) = make_float2(c1.x * a[2], c1.y * a[3]);
                }
            }
        }
    }
}

// ---------------- launch ----------------
extern "C" void kernel_launch(void* const* d_in, const int* in_sizes, int n_in,
                              void* d_out, int out_size) {
    const float* C     = (const float*)d_in[0];
    const float* Q     = (const float*)d_in[1];
    const int*   Cmask = (const int*)d_in[2];
    const int*   Qmask = (const int*)d_in[3];
    const float* w_c   = (const float*)d_in[4];
    const float* w_q   = (const float*)d_in[5];
    const float* w_mul = (const float*)d_in[6];
    const float* bias  = (const float*)d_in[7];
    float* out = (float*)d_out;

    cudaFuncSetAttribute(s_kernel, cudaFuncAttributeMaxDynamicSharedMemorySize, S_DYN);
    cudaFuncSetAttribute(final_kernel, cudaFuncAttributeMaxDynamicSharedMemorySize, F_DYN);

    s_kernel<<<BB * 8, 256, S_DYN>>>(C, Q, w_mul, w_c, w_q, bias, Qmask, Cmask);
    colmerge_kernel<<<(BB * LQ + 255) / 256, 256>>>();
    v2_kernel<<<BB * 8, 256>>>(C, Cmask);
    v2reduce_kernel<<<(BB * LQ * DD / 4 + 255) / 256, 256>>>();
    final_kernel<<<BB * 8, 256, F_DYN>>>(C, Q, Qmask, out);
}

// round 7
// speedup vs baseline: 1.3782x; 1.0133x over previous
#include <cuda_runtime.h>
#include <math.h>
#include <stdint.h>

#define BB 64
#define LC 1024
#define LQ 128
#define DD 128
#define NEG (-1e9f)

// ---------------- device scratch ----------------
__device__ float g_S[(size_t)BB * LC * LQ];      // X = exp(S), 32 MB
__device__ float g_rinv[BB * LC];                // 1 / row masked sum
__device__ float g_cps[BB * 8 * LQ];             // col partial sums (8 chunks)
__device__ float g_cinv[BB * LQ];                // 1 / col masked sum
__device__ float g_V2p[(size_t)8 * BB * LQ * DD];
__device__ float g_V2[BB * LQ * DD];

// ---------------- tf32 mma helpers ----------------
__device__ __forceinline__ void split_tf32(float x, uint32_t& hi, uint32_t& lo) {
    asm("cvt.rna.tf32.f32 %0, %1;" : "=r"(hi) : "f"(x));
    float r = x - __uint_as_float(hi);
    asm("cvt.rna.tf32.f32 %0, %1;" : "=r"(lo) : "f"(r));
}
__device__ __forceinline__ void mma8(float* d, const uint32_t* a, const uint32_t* b) {
    asm("mma.sync.aligned.m16n8k8.row.col.f32.tf32.tf32.f32 "
        "{%0,%1,%2,%3}, {%4,%5,%6,%7}, {%8,%9}, {%0,%1,%2,%3};"
        : "+f"(d[0]), "+f"(d[1]), "+f"(d[2]), "+f"(d[3])
        : "r"(a[0]), "r"(a[1]), "r"(a[2]), "r"(a[3]), "r"(b[0]), "r"(b[1]));
}
__device__ __forceinline__ void mma3(float* d, const uint32_t* ah, const uint32_t* al,
                                     const uint32_t* bh, const uint32_t* bl) {
    mma8(d, ah, bh);
    mma8(d, ah, bl);
    mma8(d, al, bh);
}

// ================= K1: S GEMM (3xTF32) + dots + X=exp(S) + sums ==========
// grid = BB*8, block 256 (8 warps = 4m x 2n, warp m32n64 via mt=2).
// Tile: 128 i x 128 j. dyn smem union: {As f32[128][36], Qs f32[128][36]} / Ss f32[128][132]
#define S_DYN (128 * 132 * 4)
__global__ __launch_bounds__(256, 2) void s_kernel(
    const float* __restrict__ Cg, const float* __restrict__ Qg,
    const float* __restrict__ w_mul, const float* __restrict__ w_c,
    const float* __restrict__ w_q, const float* __restrict__ bias,
    const int* __restrict__ Qmask, const int* __restrict__ Cmask) {
    extern __shared__ float dynf[];
    float* As = dynf;                // [128][36]
    float* Qs = dynf + 128 * 36;     // [128][36]
    float* Ss = dynf;                // [128][132] epilogue alias
    __shared__ float s_cd[128], s_qd[128];
    __shared__ float s_s2[128];
    __shared__ int s_qm[128], s_cm[128];

    int bx = blockIdx.x;
    int b = bx >> 3, tile = bx & 7, i0 = tile << 7;
    int t = threadIdx.x, wid = t >> 5, lane = t & 31;
    int g = lane >> 2, tg = lane & 3;
    int wm = wid & 3, wn = wid >> 2;
    int mb = wm << 5;          // 0,32,64,96
    int jb = wn << 6;          // 0 / 64

    if (t < 128) {
        s_qm[t] = Qmask[b * LQ + t];
        s_cm[t] = Cmask[b * LC + i0 + t];
    }

    float acc[2][8][4];
    #pragma unroll
    for (int mt = 0; mt < 2; mt++)
        #pragma unroll
        for (int nt = 0; nt < 8; nt++)
            #pragma unroll
            for (int e = 0; e < 4; e++) acc[mt][nt][e] = 0.f;

    const float* Cb = Cg + ((size_t)b * LC + i0) * DD;
    const float* Qb = Qg + (size_t)b * LQ * DD;
    int li = t >> 1, lk = (t & 1) << 4;    // loaders: 16 elems each
    float cdp = 0.f, qdp = 0.f;

    for (int kk = 0; kk < DD; kk += 32) {
        {   // As = C * w_mul ; cdot partial
            const float* src = Cb + (size_t)li * DD + kk + lk;
            float* ar = As + li * 36 + lk;
            #pragma unroll
            for (int u = 0; u < 16; u += 4) {
                float4 v = *(const float4*)(src + u);
                float4 m = *(const float4*)(w_mul + kk + lk + u);
                float4 c = *(const float4*)(w_c + kk + lk + u);
                cdp += v.x * c.x + v.y * c.y + v.z * c.z + v.w * c.w;
                ar[u] = v.x * m.x; ar[u + 1] = v.y * m.y;
                ar[u + 2] = v.z * m.z; ar[u + 3] = v.w * m.w;
            }
        }
        {   // Qs ; qdot partial
            const float* src = Qb + (size_t)li * DD + kk + lk;
            float* qr = Qs + li * 36 + lk;
            #pragma unroll
            for (int u = 0; u < 16; u += 4) {
                float4 v = *(const float4*)(src + u);
                float4 w = *(const float4*)(w_q + kk + lk + u);
                qdp += v.x * w.x + v.y * w.y + v.z * w.z + v.w * w.w;
                qr[u] = v.x; qr[u + 1] = v.y; qr[u + 2] = v.z; qr[u + 3] = v.w;
            }
        }
        __syncthreads();
        #pragma unroll
        for (int k8 = 0; k8 < 4; k8++) {
            int kb = k8 << 3;
            uint32_t ah[2][4], al[2][4];
            #pragma unroll
            for (int mt = 0; mt < 2; mt++) {
                int m0 = mb + mt * 16;
                split_tf32(As[(m0 + g) * 36 + kb + tg],         ah[mt][0], al[mt][0]);
                split_tf32(As[(m0 + g + 8) * 36 + kb + tg],     ah[mt][1], al[mt][1]);
                split_tf32(As[(m0 + g) * 36 + kb + tg + 4],     ah[mt][2], al[mt][2]);
                split_tf32(As[(m0 + g + 8) * 36 + kb + tg + 4], ah[mt][3], al[mt][3]);
            }
            #pragma unroll
            for (int nt = 0; nt < 8; nt++) {
                uint32_t bh[2], bl[2];
                split_tf32(Qs[(jb + nt * 8 + g) * 36 + kb + tg],     bh[0], bl[0]);
                split_tf32(Qs[(jb + nt * 8 + g) * 36 + kb + tg + 4], bh[1], bl[1]);
                mma3(acc[0][nt], ah[0], al[0], bh, bl);
                mma3(acc[1][nt], ah[1], al[1], bh, bl);
            }
        }
        __syncthreads();
    }

    // reduce dots (pairs share a row)
    cdp += __shfl_xor_sync(0xffffffffu, cdp, 1);
    if ((t & 1) == 0) s_cd[li] = cdp;
    qdp += __shfl_xor_sync(0xffffffffu, qdp, 1);
    if ((t & 1) == 0) s_qd[li] = qdp;
    __syncthreads();

    // finalize S into Ss (overwrites As/Qs)
    {
        float bi = bias[0];
        #pragma unroll
        for (int mt = 0; mt < 2; mt++) {
            int m0 = mb + mt * 16;
            float cd0 = s_cd[m0 + g] + bi, cd1 = s_cd[m0 + g + 8] + bi;
            #pragma unroll
            for (int nt = 0; nt < 8; nt++) {
                int c0 = jb + nt * 8 + 2 * tg;
                float q0 = s_qd[c0], q1 = s_qd[c0 + 1];
                Ss[(m0 + g) * 132 + c0]     = acc[mt][nt][0] + cd0 + q0;
                Ss[(m0 + g) * 132 + c0 + 1] = acc[mt][nt][1] + cd0 + q1;
                Ss[(m0 + g + 8) * 132 + c0]     = acc[mt][nt][2] + cd1 + q0;
                Ss[(m0 + g + 8) * 132 + c0 + 1] = acc[mt][nt][3] + cd1 + q1;
            }
        }
    }
    __syncthreads();

    // phase A: X = exp(S) (sole exp pass) -> Ss & g_S ; masked row sums
    {
        int i = t >> 1, j0 = (t & 1) << 6;
        float sm = 0.f;
        float* dst = g_S + ((size_t)(b * LC + i0 + i)) * LQ + j0;
        #pragma unroll
        for (int u = 0; u < 64; u += 4) {
            float4 v = *(const float4*)&Ss[i * 132 + j0 + u];
            int4 m = *(const int4*)&s_qm[j0 + u];
            float4 x = make_float4(__expf(v.x), __expf(v.y), __expf(v.z), __expf(v.w));
            *(float4*)&Ss[i * 132 + j0 + u] = x;
            *(float4*)(dst + u) = x;
            sm += (m.x ? x.x : 0.f) + (m.y ? x.y : 0.f)
                + (m.z ? x.z : 0.f) + (m.w ? x.w : 0.f);
        }
        sm += __shfl_xor_sync(0xffffffffu, sm, 1);
        if ((t & 1) == 0) g_rinv[b * LC + i0 + i] = 1.f / sm;
    }
    __syncthreads();

    // phase B: masked column partial sums over this tile's 128 rows
    {
        int j = t & 127, ih = t >> 7;
        float s = 0.f;
        #pragma unroll 8
        for (int r = 0; r < 64; r++) {
            int i = ih * 64 + r;
            s += s_cm[i] ? Ss[i * 132 + j] : 0.f;
        }
        if (ih == 1) s_s2[j] = s;
        __syncthreads();
        if (ih == 0)
            g_cps[(b * 8 + tile) * LQ + j] = s + s_s2[j];
    }
}

// ================= K2: merge column partial sums =================
__global__ __launch_bounds__(256) void colmerge_kernel() {
    int idx = blockIdx.x * blockDim.x + threadIdx.x;
    if (idx >= BB * LQ) return;
    int b = idx >> 7, j = idx & 127;
    float S = 0.f;
    #pragma unroll
    for (int g = 0; g < 8; g++) S += g_cps[(b * 8 + g) * LQ + j];
    g_cinv[idx] = 1.f / S;
}

// ================= K3: V2 partial = P2^T(chunk) @ C(chunk), 3xTF32 =====
// grid = BB*8, block 256 (8 warps = 4m x 2n, warp m32n64). K=128 per chunk.
__global__ __launch_bounds__(256, 2) void v2_kernel(
    const float* __restrict__ Cg, const int* __restrict__ Cmask) {
    __shared__ float Ps[32 * 136];   // k-major: [i'][j]
    __shared__ float Cs[32 * 136];   // k-major: [i'][d]
    __shared__ float s_ci[128];
    __shared__ int s_cm[128];
    int b = blockIdx.x >> 3, gc = blockIdx.x & 7;
    int t = threadIdx.x, wid = t >> 5, lane = t & 31;
    int g = lane >> 2, tg = lane & 3;
    int wm = wid >> 1, wn = wid & 1;
    int mb0 = wm << 5;   // j base
    int nb = wn << 6;    // d base
    if (t < 128) {
        s_ci[t] = g_cinv[b * LQ + t];
        s_cm[t] = Cmask[b * LC + gc * 128 + t];
    }
    __syncthreads();

    float acc[2][8][4];
    #pragma unroll
    for (int mt = 0; mt < 2; mt++)
        #pragma unroll
        for (int nt = 0; nt < 8; nt++)
            #pragma unroll
            for (int e = 0; e < 4; e++) acc[mt][nt][e] = 0.f;

    int li = t >> 3, lj = (t & 7) << 4;
    for (int ik = 0; ik < 128; ik += 32) {
        {
            const float* srow = g_S + ((size_t)(b * LC + gc * 128 + ik + li)) * LQ + lj;
            int msk = s_cm[ik + li];
            float* pr = Ps + li * 136 + lj;
            #pragma unroll
            for (int u = 0; u < 16; u += 4) {
                float4 v = *(const float4*)(srow + u);
                pr[u]     = msk ? v.x * s_ci[lj + u]     : 0.f;
                pr[u + 1] = msk ? v.y * s_ci[lj + u + 1] : 0.f;
                pr[u + 2] = msk ? v.z * s_ci[lj + u + 2] : 0.f;
                pr[u + 3] = msk ? v.w * s_ci[lj + u + 3] : 0.f;
            }
            const float* crow = Cg + ((size_t)(b * LC + gc * 128 + ik + li)) * DD + lj;
            float* cr = Cs + li * 136 + lj;
            #pragma unroll
            for (int u = 0; u < 16; u += 4) {
                float4 v = *(const float4*)(crow + u);
                cr[u] = v.x; cr[u + 1] = v.y; cr[u + 2] = v.z; cr[u + 3] = v.w;
            }
        }
        __syncthreads();
        #pragma unroll
        for (int k8 = 0; k8 < 4; k8++) {
            int kb = k8 << 3;
            uint32_t ah[2][4], al[2][4];
            #pragma unroll
            for (int mt = 0; mt < 2; mt++) {
                int m0 = mb0 + mt * 16;
                split_tf32(Ps[(kb + tg) * 136 + m0 + g],         ah[mt][0], al[mt][0]);
                split_tf32(Ps[(kb + tg) * 136 + m0 + g + 8],     ah[mt][1], al[mt][1]);
                split_tf32(Ps[(kb + tg + 4) * 136 + m0 + g],     ah[mt][2], al[mt][2]);
                split_tf32(Ps[(kb + tg + 4) * 136 + m0 + g + 8], ah[mt][3], al[mt][3]);
            }
            #pragma unroll
            for (int nt = 0; nt < 8; nt++) {
                uint32_t bh[2], bl[2];
                split_tf32(Cs[(kb + tg) * 136 + nb + nt * 8 + g],     bh[0], bl[0]);
                split_tf32(Cs[(kb + tg + 4) * 136 + nb + nt * 8 + g], bh[1], bl[1]);
                mma3(acc[0][nt], ah[0], al[0], bh, bl);
                mma3(acc[1][nt], ah[1], al[1], bh, bl);
            }
        }
        __syncthreads();
    }

    float* Vp = g_V2p + (size_t)(b * 8 + gc) * LQ * DD;
    #pragma unroll
    for (int mt = 0; mt < 2; mt++) {
        int r0 = mb0 + mt * 16 + g;
        #pragma unroll
        for (int nt = 0; nt < 8; nt++) {
            int d = nb + nt * 8 + 2 * tg;
            *(float2*)(Vp + (size_t)r0 * DD + d)       = make_float2(acc[mt][nt][0], acc[mt][nt][1]);
            *(float2*)(Vp + (size_t)(r0 + 8) * DD + d) = make_float2(acc[mt][nt][2], acc[mt][nt][3]);
        }
    }
}

__global__ __launch_bounds__(256) void v2reduce_kernel() {
    int vec = blockIdx.x * blockDim.x + threadIdx.x;
    const int per_b = LQ * DD / 4;
    if (vec >= BB * per_b) return;
    int b = vec / per_b;
    int off = vec % per_b;
    float4 s = make_float4(0.f, 0.f, 0.f, 0.f);
    #pragma unroll
    for (int g = 0; g < 8; g++) {
        float4 v = ((const float4*)(g_V2p + (size_t)(b * 8 + g) * LQ * DD))[off];
        s.x += v.x; s.y += v.y; s.z += v.z; s.w += v.w;
    }
    ((float4*)g_V2)[vec] = s;
}

// ================= K4: A = P1@Q, Bm = P1@V2 (3xTF32) =====================
// grid = BB*8, block 256 (8 warps = 4m x 2n, warp m32n64). Tile 128 i x 128 n.
#define F_DYN ((128 * 130 + 16 * 136) * 4)
__global__ __launch_bounds__(256, 2) void final_kernel(
    const float* __restrict__ Cg, const float* __restrict__ Qg,
    const int* __restrict__ Qmask, float* __restrict__ out) {
    extern __shared__ float dynf[];
    float* Ps = dynf;                // [128][130] m-major [i][j], full K
    float* Bs = dynf + 128 * 130;    // [16][136] k-major chunk [j'][d]
    int bx = blockIdx.x;
    int b = bx >> 3, i0 = (bx & 7) << 7;
    int t = threadIdx.x, wid = t >> 5, lane = t & 31;
    int g = lane >> 2, tg = lane & 3;
    int wm = wid & 3, wn = wid >> 2;
    int mb = wm << 5, nb = wn << 6;

    {   // build P1 tile: 2 threads per row, 64 j each (no exp)
        int i = t >> 1, j0 = (t & 1) << 6;
        int gi = b * LC + i0 + i;
        float ri = __ldg(&g_rinv[gi]);
        const float* srow = g_S + (size_t)gi * LQ + j0;
        const int* qm = Qmask + b * LQ + j0;
        float* pr = Ps + i * 130 + j0;
        #pragma unroll
        for (int u = 0; u < 64; u += 4) {
            float4 v = *(const float4*)(srow + u);
            int4 m = *(const int4*)(qm + u);
            pr[u]     = m.x ? v.x * ri : 0.f;
            pr[u + 1] = m.y ? v.y * ri : 0.f;
            pr[u + 2] = m.z ? v.z * ri : 0.f;
            pr[u + 3] = m.w ? v.w * ri : 0.f;
        }
    }
    __syncthreads();

    int lk = t >> 4, ld0 = (t & 15) << 3;
    #pragma unroll
    for (int pass = 0; pass < 2; pass++) {
        const float* Bsrc = pass ? (g_V2 + (size_t)b * LQ * DD) : (Qg + (size_t)b * LQ * DD);
        float acc[2][8][4];
        #pragma unroll
        for (int mt = 0; mt < 2; mt++)
            #pragma unroll
            for (int nt = 0; nt < 8; nt++)
                #pragma unroll
                for (int e = 0; e < 4; e++) acc[mt][nt][e] = 0.f;

        for (int kk = 0; kk < LQ; kk += 16) {
            {
                const float* br = Bsrc + (size_t)(kk + lk) * DD + ld0;
                float4 v0 = *(const float4*)br;
                float4 v1 = *(const float4*)(br + 4);
                float* bd = Bs + lk * 136 + ld0;
                bd[0] = v0.x; bd[1] = v0.y; bd[2] = v0.z; bd[3] = v0.w;
                bd[4] = v1.x; bd[5] = v1.y; bd[6] = v1.z; bd[7] = v1.w;
            }
            __syncthreads();
            #pragma unroll
            for (int k8 = 0; k8 < 2; k8++) {
                int kb = k8 << 3;
                uint32_t ah[2][4], al[2][4];
                #pragma unroll
                for (int mt = 0; mt < 2; mt++) {
                    int m0 = mb + mt * 16;
                    split_tf32(Ps[(m0 + g) * 130 + kk + kb + tg],         ah[mt][0], al[mt][0]);
                    split_tf32(Ps[(m0 + g + 8) * 130 + kk + kb + tg],     ah[mt][1], al[mt][1]);
                    split_tf32(Ps[(m0 + g) * 130 + kk + kb + tg + 4],     ah[mt][2], al[mt][2]);
                    split_tf32(Ps[(m0 + g + 8) * 130 + kk + kb + tg + 4], ah[mt][3], al[mt][3]);
                }
                #pragma unroll
                for (int nt = 0; nt < 8; nt++) {
                    uint32_t bh[2], bl[2];
                    split_tf32(Bs[(kb + tg) * 136 + nb + nt * 8 + g],     bh[0], bl[0]);
                    split_tf32(Bs[(kb + tg + 4) * 136 + nb + nt * 8 + g], bh[1], bl[1]);
                    mma3(acc[0][nt], ah[0], al[0], bh, bl);
                    mma3(acc[1][nt], ah[1], al[1], bh, bl);
                }
            }
            __syncthreads();
        }

        // epilogue
        #pragma unroll
        for (int mt = 0; mt < 2; mt++) {
            int r0 = i0 + mb + mt * 16 + g, r1 = r0 + 8;
            const float* c0p = Cg + ((size_t)(b * LC + r0)) * DD;
            const float* c1p = Cg + ((size_t)(b * LC + r1)) * DD;
            float* o0 = out + ((size_t)(b * LC + r0)) * (4 * DD);
            float* o1 = out + ((size_t)(b * LC + r1)) * (4 * DD);
            #pragma unroll
            for (int nt = 0; nt < 8; nt++) {
                int d = nb + nt * 8 + 2 * tg;
                float2 c0 = *(const float2*)(c0p + d);
                float2 c1 = *(const float2*)(c1p + d);
                float* a = acc[mt][nt];
                if (pass == 0) {
                    *(float2*)(o0 + d) = c0;
                    *(float2*)(o1 + d) = c1;
                    *(float2*)(o0 + DD + d) = make_float2(a[0], a[1]);
                    *(float2*)(o1 + DD + d) = make_float2(a[2], a[3]);
                    *(float2*)(o0 + 2 * DD + d) = make_float2(c0.x * a[0], c0.y * a[1]);
                    *(float2*)(o1 + 2 * DD + d) = make_float2(c1.x * a[2], c1.y * a[3]);
                } else {
                    *(float2*)(o0 + 3 * DD + d) = make_float2(c0.x * a[0], c0.y * a[1]);
                    *(float2*)(o1 + 3 * DD + d) = make_float2(c1.x * a[2], c1.y * a[3]);
                }
            }
        }
    }
}

// ---------------- launch ----------------
extern "C" void kernel_launch(void* const* d_in, const int* in_sizes, int n_in,
                              void* d_out, int out_size) {
    const float* C     = (const float*)d_in[0];
    const float* Q     = (const float*)d_in[1];
    const int*   Cmask = (const int*)d_in[2];
    const int*   Qmask = (const int*)d_in[3];
    const float* w_c   = (const float*)d_in[4];
    const float* w_q   = (const float*)d_in[5];
    const float* w_mul = (const float*)d_in[6];
    const float* bias  = (const float*)d_in[7];
    float* out = (float*)d_out;

    cudaFuncSetAttribute(s_kernel, cudaFuncAttributeMaxDynamicSharedMemorySize, S_DYN);
    cudaFuncSetAttribute(final_kernel, cudaFuncAttributeMaxDynamicSharedMemorySize, F_DYN);

    s_kernel<<<BB * 8, 256, S_DYN>>>(C, Q, w_mul, w_c, w_q, bias, Qmask, Cmask);
    colmerge_kernel<<<(BB * LQ + 255) / 256, 256>>>();
    v2_kernel<<<BB * 8, 256>>>(C, Cmask);
    v2reduce_kernel<<<(BB * LQ * DD / 4 + 255) / 256, 256>>>();
    final_kernel<<<BB * 8, 256, F_DYN>>>(C, Q, Qmask, out);
}

// round 8
// speedup vs baseline: 1.4930x; 1.0833x over previous
#include <cuda_runtime.h>
#include <math.h>
#include <stdint.h>

#define BB 64
#define LC 1024
#define LQ 128
#define DD 128
#define NEG (-1e9f)

// ---------------- device scratch ----------------
__device__ float g_S[(size_t)BB * LC * LQ];      // X = exp(S), 32 MB
__device__ float g_cdot[BB * LC];
__device__ float g_qdot[BB * LQ];
__device__ float g_rinv[BB * LC];
__device__ float g_cps[BB * 8 * LQ];
__device__ float g_cinv[BB * LQ];
__device__ float g_V2p[(size_t)8 * BB * LQ * DD];
__device__ float g_V2[BB * LQ * DD];

// ---------------- helpers ----------------
__device__ __forceinline__ void split_tf32(float x, uint32_t& hi, uint32_t& lo) {
    asm("cvt.rna.tf32.f32 %0, %1;" : "=r"(hi) : "f"(x));
    float r = x - __uint_as_float(hi);
    asm("cvt.rna.tf32.f32 %0, %1;" : "=r"(lo) : "f"(r));
}
__device__ __forceinline__ void mma8(float* d, const uint32_t* a, const uint32_t* b) {
    asm("mma.sync.aligned.m16n8k8.row.col.f32.tf32.tf32.f32 "
        "{%0,%1,%2,%3}, {%4,%5,%6,%7}, {%8,%9}, {%0,%1,%2,%3};"
        : "+f"(d[0]), "+f"(d[1]), "+f"(d[2]), "+f"(d[3])
        : "r"(a[0]), "r"(a[1]), "r"(a[2]), "r"(a[3]), "r"(b[0]), "r"(b[1]));
}
__device__ __forceinline__ void mma3(float* d, const uint32_t* ah, const uint32_t* al,
                                     const uint32_t* bh, const uint32_t* bl) {
    mma8(d, ah, bh);
    mma8(d, ah, bl);
    mma8(d, al, bh);
}
__device__ __forceinline__ void cpa16(uint32_t dst, const float* src) {
    asm volatile("cp.async.cg.shared.global [%0], [%1], 16;" :: "r"(dst), "l"(src));
}
#define CP_COMMIT() asm volatile("cp.async.commit_group;" ::: "memory")
#define CP_WAIT(n)  asm volatile("cp.async.wait_group %0;" :: "n"(n) : "memory")

// ================= K0: row dots =================
__global__ __launch_bounds__(256) void dots_kernel(
    const float* __restrict__ Cg, const float* __restrict__ Qg,
    const float* __restrict__ w_c, const float* __restrict__ w_q) {
    int warp = (blockIdx.x * blockDim.x + threadIdx.x) >> 5;
    int lane = threadIdx.x & 31;
    if (warp < BB * LC) {
        float4 v = ((const float4*)(Cg + (size_t)warp * DD))[lane];
        float4 w = ((const float4*)w_c)[lane];
        float s = v.x * w.x + v.y * w.y + v.z * w.z + v.w * w.w;
        #pragma unroll
        for (int o = 16; o; o >>= 1) s += __shfl_xor_sync(0xffffffffu, s, o);
        if (lane == 0) g_cdot[warp] = s;
    } else {
        int r = warp - BB * LC;
        if (r < BB * LQ) {
            float4 v = ((const float4*)(Qg + (size_t)r * DD))[lane];
            float4 w = ((const float4*)w_q)[lane];
            float s = v.x * w.x + v.y * w.y + v.z * w.z + v.w * w.w;
            #pragma unroll
            for (int o = 16; o; o >>= 1) s += __shfl_xor_sync(0xffffffffu, s, o);
            if (lane == 0) g_qdot[r] = s;
        }
    }
}

// ================= K1: S GEMM (3xTF32, cp.async pipelined) ===============
// grid = BB*8, block 256 (8 warps = 4m x 2n, warp m32n64). Tile 128i x 128j.
// dyn: A0,A1,Q0,Q1 each [128][36] raw f32; Ss [128][132] alias.
#define S_DYN (4 * 128 * 36 * 4)
__global__ __launch_bounds__(256, 2) void s_kernel(
    const float* __restrict__ Cg, const float* __restrict__ Qg,
    const float* __restrict__ w_mul, const float* __restrict__ bias,
    const int* __restrict__ Qmask, const int* __restrict__ Cmask) {
    extern __shared__ float dynf[];
    float* Ab[2] = {dynf, dynf + 128 * 36};
    float* Qb2[2] = {dynf + 2 * 128 * 36, dynf + 3 * 128 * 36};
    float* Ss = dynf;                // [128][132] epilogue alias
    __shared__ float s_cd[128], s_qd[128], s_wm[128];
    __shared__ float s_s2[128];
    __shared__ int s_qm[128], s_cm[128];

    int bx = blockIdx.x;
    int b = bx >> 3, tile = bx & 7, i0 = tile << 7;
    int t = threadIdx.x, wid = t >> 5, lane = t & 31;
    int g = lane >> 2, tg = lane & 3;
    int wm_ = wid & 3, wn = wid >> 2;
    int mb = wm_ << 5;
    int jb = wn << 6;

    if (t < 128) {
        s_qm[t] = Qmask[b * LQ + t];
        s_cm[t] = Cmask[b * LC + i0 + t];
        s_wm[t] = w_mul[t];
        s_cd[t] = g_cdot[b * LC + i0 + t];
        s_qd[t] = g_qdot[b * LQ + t];
    }

    const float* Cb = Cg + ((size_t)b * LC + i0) * DD;
    const float* Qb = Qg + (size_t)b * LQ * DD;
    uint32_t aB[2], qB[2];
    aB[0] = (uint32_t)__cvta_generic_to_shared(Ab[0]);
    aB[1] = (uint32_t)__cvta_generic_to_shared(Ab[1]);
    qB[0] = (uint32_t)__cvta_generic_to_shared(Qb2[0]);
    qB[1] = (uint32_t)__cvta_generic_to_shared(Qb2[1]);

    float acc[2][8][4];
    #pragma unroll
    for (int mt = 0; mt < 2; mt++)
        #pragma unroll
        for (int nt = 0; nt < 8; nt++)
            #pragma unroll
            for (int e = 0; e < 4; e++) acc[mt][nt][e] = 0.f;

    // issue stage: 128 rows x 32 f32 per array; 1024 16B-chunks -> 4/thread each
    #define S_ISSUE(buf, kk) {                                              \
        _Pragma("unroll")                                                   \
        for (int u = 0; u < 4; u++) {                                       \
            int gid = u * 256 + t, row = gid >> 3, ch = gid & 7;            \
            cpa16(aB[buf] + (row * 36 + ch * 4) * 4, Cb + (size_t)row * DD + (kk) + ch * 4); \
            cpa16(qB[buf] + (row * 36 + ch * 4) * 4, Qb + (size_t)row * DD + (kk) + ch * 4); \
        }                                                                   \
        CP_COMMIT(); }

    S_ISSUE(0, 0)
    #pragma unroll
    for (int s = 0; s < 4; s++) {
        if (s < 3) S_ISSUE((s + 1) & 1, (s + 1) * 32)
        if (s < 3) { CP_WAIT(1); } else { CP_WAIT(0); }
        __syncthreads();
        const float* As = Ab[s & 1];
        const float* Qs = Qb2[s & 1];
        int kk = s * 32;
        #pragma unroll
        for (int k8 = 0; k8 < 4; k8++) {
            int kb = k8 << 3;
            float wm0 = s_wm[kk + kb + tg], wm1 = s_wm[kk + kb + tg + 4];
            uint32_t ah[2][4], al[2][4];
            #pragma unroll
            for (int mt = 0; mt < 2; mt++) {
                int m0 = mb + mt * 16;
                split_tf32(As[(m0 + g) * 36 + kb + tg] * wm0,         ah[mt][0], al[mt][0]);
                split_tf32(As[(m0 + g + 8) * 36 + kb + tg] * wm0,     ah[mt][1], al[mt][1]);
                split_tf32(As[(m0 + g) * 36 + kb + tg + 4] * wm1,     ah[mt][2], al[mt][2]);
                split_tf32(As[(m0 + g + 8) * 36 + kb + tg + 4] * wm1, ah[mt][3], al[mt][3]);
            }
            #pragma unroll
            for (int nt = 0; nt < 8; nt++) {
                uint32_t bh[2], bl[2];
                split_tf32(Qs[(jb + nt * 8 + g) * 36 + kb + tg],     bh[0], bl[0]);
                split_tf32(Qs[(jb + nt * 8 + g) * 36 + kb + tg + 4], bh[1], bl[1]);
                mma3(acc[0][nt], ah[0], al[0], bh, bl);
                mma3(acc[1][nt], ah[1], al[1], bh, bl);
            }
        }
        __syncthreads();
    }

    // finalize S into Ss
    {
        float bi = bias[0];
        #pragma unroll
        for (int mt = 0; mt < 2; mt++) {
            int m0 = mb + mt * 16;
            float cd0 = s_cd[m0 + g] + bi, cd1 = s_cd[m0 + g + 8] + bi;
            #pragma unroll
            for (int nt = 0; nt < 8; nt++) {
                int c0 = jb + nt * 8 + 2 * tg;
                float q0 = s_qd[c0], q1 = s_qd[c0 + 1];
                Ss[(m0 + g) * 132 + c0]     = acc[mt][nt][0] + cd0 + q0;
                Ss[(m0 + g) * 132 + c0 + 1] = acc[mt][nt][1] + cd0 + q1;
                Ss[(m0 + g + 8) * 132 + c0]     = acc[mt][nt][2] + cd1 + q0;
                Ss[(m0 + g + 8) * 132 + c0 + 1] = acc[mt][nt][3] + cd1 + q1;
            }
        }
    }
    __syncthreads();

    // phase A: X = exp(S) -> Ss & g_S ; masked row sums
    {
        int i = t >> 1, j0 = (t & 1) << 6;
        float sm = 0.f;
        float* dst = g_S + ((size_t)(b * LC + i0 + i)) * LQ + j0;
        #pragma unroll
        for (int u = 0; u < 64; u += 4) {
            float4 v = *(const float4*)&Ss[i * 132 + j0 + u];
            int4 m = *(const int4*)&s_qm[j0 + u];
            float4 x = make_float4(__expf(v.x), __expf(v.y), __expf(v.z), __expf(v.w));
            *(float4*)&Ss[i * 132 + j0 + u] = x;
            *(float4*)(dst + u) = x;
            sm += (m.x ? x.x : 0.f) + (m.y ? x.y : 0.f)
                + (m.z ? x.z : 0.f) + (m.w ? x.w : 0.f);
        }
        sm += __shfl_xor_sync(0xffffffffu, sm, 1);
        if ((t & 1) == 0) g_rinv[b * LC + i0 + i] = 1.f / sm;
    }
    __syncthreads();

    // phase B: masked column partial sums
    {
        int j = t & 127, ih = t >> 7;
        float s = 0.f;
        #pragma unroll 8
        for (int r = 0; r < 64; r++) {
            int i = ih * 64 + r;
            s += s_cm[i] ? Ss[i * 132 + j] : 0.f;
        }
        if (ih == 1) s_s2[j] = s;
        __syncthreads();
        if (ih == 0)
            g_cps[(b * 8 + tile) * LQ + j] = s + s_s2[j];
    }
}

// ================= K2: merge column partial sums =================
__global__ __launch_bounds__(256) void colmerge_kernel() {
    int idx = blockIdx.x * blockDim.x + threadIdx.x;
    if (idx >= BB * LQ) return;
    int b = idx >> 7, j = idx & 127;
    float S = 0.f;
    #pragma unroll
    for (int g = 0; g < 8; g++) S += g_cps[(b * 8 + g) * LQ + j];
    g_cinv[idx] = 1.f / S;
}

// ================= K3: V2 partial (3xTF32, cp.async pipelined) ===========
// grid = BB*8, block 256. dyn: X0,X1,C0,C1 each [32][136] raw.
#define V2_DYN (4 * 32 * 136 * 4)
__global__ __launch_bounds__(256, 2) void v2_kernel(
    const float* __restrict__ Cg, const int* __restrict__ Cmask) {
    extern __shared__ float dynf[];
    float* Xb[2] = {dynf, dynf + 32 * 136};
    float* Cb2[2] = {dynf + 2 * 32 * 136, dynf + 3 * 32 * 136};
    __shared__ int s_cm[128];
    int b = blockIdx.x >> 3, gc = blockIdx.x & 7;
    int t = threadIdx.x, wid = t >> 5, lane = t & 31;
    int g = lane >> 2, tg = lane & 3;
    int wm_ = wid >> 1, wn = wid & 1;
    int mb0 = wm_ << 5;
    int nb = wn << 6;
    if (t < 128) s_cm[t] = Cmask[b * LC + gc * 128 + t];

    float ci_[2][2];
    #pragma unroll
    for (int mt = 0; mt < 2; mt++) {
        ci_[mt][0] = g_cinv[b * LQ + mb0 + mt * 16 + g];
        ci_[mt][1] = g_cinv[b * LQ + mb0 + mt * 16 + g + 8];
    }

    const float* Sb = g_S + ((size_t)(b * LC + gc * 128)) * LQ;
    const float* Cb = Cg + ((size_t)(b * LC + gc * 128)) * DD;
    uint32_t xB[2], cB[2];
    xB[0] = (uint32_t)__cvta_generic_to_shared(Xb[0]);
    xB[1] = (uint32_t)__cvta_generic_to_shared(Xb[1]);
    cB[0] = (uint32_t)__cvta_generic_to_shared(Cb2[0]);
    cB[1] = (uint32_t)__cvta_generic_to_shared(Cb2[1]);

    float acc[2][8][4];
    #pragma unroll
    for (int mt = 0; mt < 2; mt++)
        #pragma unroll
        for (int nt = 0; nt < 8; nt++)
            #pragma unroll
            for (int e = 0; e < 4; e++) acc[mt][nt][e] = 0.f;

    // stage: 32 rows x 128 f32 per array; 1024 chunks -> 4/thread each
    #define V_ISSUE(buf, ik) {                                              \
        _Pragma("unroll")                                                   \
        for (int u = 0; u < 4; u++) {                                       \
            int gid = u * 256 + t, row = gid >> 5, ch = gid & 31;           \
            cpa16(xB[buf] + (row * 136 + ch * 4) * 4, Sb + (size_t)((ik) + row) * LQ + ch * 4); \
            cpa16(cB[buf] + (row * 136 + ch * 4) * 4, Cb + (size_t)((ik) + row) * DD + ch * 4); \
        }                                                                   \
        CP_COMMIT(); }

    V_ISSUE(0, 0)
    #pragma unroll
    for (int s = 0; s < 4; s++) {
        if (s < 3) V_ISSUE((s + 1) & 1, (s + 1) * 32)
        if (s < 3) { CP_WAIT(1); } else { CP_WAIT(0); }
        __syncthreads();
        const float* Xs = Xb[s & 1];
        const float* Cs = Cb2[s & 1];
        int ik = s * 32;
        #pragma unroll
        for (int k8 = 0; k8 < 4; k8++) {
            int kb = k8 << 3;
            float f0 = s_cm[ik + kb + tg] ? 1.f : 0.f;
            float f1 = s_cm[ik + kb + tg + 4] ? 1.f : 0.f;
            uint32_t ah[2][4], al[2][4];
            #pragma unroll
            for (int mt = 0; mt < 2; mt++) {
                int m0 = mb0 + mt * 16;
                split_tf32(Xs[(kb + tg) * 136 + m0 + g] * (f0 * ci_[mt][0]),         ah[mt][0], al[mt][0]);
                split_tf32(Xs[(kb + tg) * 136 + m0 + g + 8] * (f0 * ci_[mt][1]),     ah[mt][1], al[mt][1]);
                split_tf32(Xs[(kb + tg + 4) * 136 + m0 + g] * (f1 * ci_[mt][0]),     ah[mt][2], al[mt][2]);
                split_tf32(Xs[(kb + tg + 4) * 136 + m0 + g + 8] * (f1 * ci_[mt][1]), ah[mt][3], al[mt][3]);
            }
            #pragma unroll
            for (int nt = 0; nt < 8; nt++) {
                uint32_t bh[2], bl[2];
                split_tf32(Cs[(kb + tg) * 136 + nb + nt * 8 + g],     bh[0], bl[0]);
                split_tf32(Cs[(kb + tg + 4) * 136 + nb + nt * 8 + g], bh[1], bl[1]);
                mma3(acc[0][nt], ah[0], al[0], bh, bl);
                mma3(acc[1][nt], ah[1], al[1], bh, bl);
            }
        }
        __syncthreads();
    }

    float* Vp = g_V2p + (size_t)(b * 8 + gc) * LQ * DD;
    #pragma unroll
    for (int mt = 0; mt < 2; mt++) {
        int r0 = mb0 + mt * 16 + g;
        #pragma unroll
        for (int nt = 0; nt < 8; nt++) {
            int d = nb + nt * 8 + 2 * tg;
            *(float2*)(Vp + (size_t)r0 * DD + d)       = make_float2(acc[mt][nt][0], acc[mt][nt][1]);
            *(float2*)(Vp + (size_t)(r0 + 8) * DD + d) = make_float2(acc[mt][nt][2], acc[mt][nt][3]);
        }
    }
}

__global__ __launch_bounds__(256) void v2reduce_kernel() {
    int vec = blockIdx.x * blockDim.x + threadIdx.x;
    const int per_b = LQ * DD / 4;
    if (vec >= BB * per_b) return;
    int b = vec / per_b;
    int off = vec % per_b;
    float4 s = make_float4(0.f, 0.f, 0.f, 0.f);
    #pragma unroll
    for (int g = 0; g < 8; g++) {
        float4 v = ((const float4*)(g_V2p + (size_t)(b * 8 + g) * LQ * DD))[off];
        s.x += v.x; s.y += v.y; s.z += v.z; s.w += v.w;
    }
    ((float4*)g_V2)[vec] = s;
}

// ================= K4: A = P1@Q, Bm = P1@V2 (3xTF32, cp.async Bs) ========
// grid = BB*8, block 256. dyn: Ps [128][130] + Bs0,Bs1 [16][136].
#define F_DYN ((128 * 130 + 2 * 16 * 136) * 4)
__global__ __launch_bounds__(256, 2) void final_kernel(
    const float* __restrict__ Cg, const float* __restrict__ Qg,
    const int* __restrict__ Qmask, float* __restrict__ out) {
    extern __shared__ float dynf[];
    float* Ps = dynf;                 // [128][130]
    float* Bsb[2] = {dynf + 128 * 130, dynf + 128 * 130 + 16 * 136};
    int bx = blockIdx.x;
    int b = bx >> 3, i0 = (bx & 7) << 7;
    int t = threadIdx.x, wid = t >> 5, lane = t & 31;
    int g = lane >> 2, tg = lane & 3;
    int wm_ = wid & 3, wn = wid >> 2;
    int mb = wm_ << 5, nb = wn << 6;
    uint32_t bB[2];
    bB[0] = (uint32_t)__cvta_generic_to_shared(Bsb[0]);
    bB[1] = (uint32_t)__cvta_generic_to_shared(Bsb[1]);

    {   // build P1 tile (no exp)
        int i = t >> 1, j0 = (t & 1) << 6;
        int gi = b * LC + i0 + i;
        float ri = __ldg(&g_rinv[gi]);
        const float* srow = g_S + (size_t)gi * LQ + j0;
        const int* qm = Qmask + b * LQ + j0;
        float* pr = Ps + i * 130 + j0;
        #pragma unroll
        for (int u = 0; u < 64; u += 4) {
            float4 v = *(const float4*)(srow + u);
            int4 m = *(const int4*)(qm + u);
            pr[u]     = m.x ? v.x * ri : 0.f;
            pr[u + 1] = m.y ? v.y * ri : 0.f;
            pr[u + 2] = m.z ? v.z * ri : 0.f;
            pr[u + 3] = m.w ? v.w * ri : 0.f;
        }
    }
    __syncthreads();

    // Bs stage: 16 rows x 128 f32 = 512 chunks -> 2/thread
    #define F_ISSUE(buf, src, kk) {                                         \
        _Pragma("unroll")                                                   \
        for (int u = 0; u < 2; u++) {                                       \
            int gid = u * 256 + t, row = gid >> 5, ch = gid & 31;           \
            cpa16(bB[buf] + (row * 136 + ch * 4) * 4, (src) + (size_t)((kk) + row) * DD + ch * 4); \
        }                                                                   \
        CP_COMMIT(); }

    #pragma unroll
    for (int pass = 0; pass < 2; pass++) {
        const float* Bsrc = pass ? (g_V2 + (size_t)b * LQ * DD) : (Qg + (size_t)b * LQ * DD);
        float acc[2][8][4];
        #pragma unroll
        for (int mt = 0; mt < 2; mt++)
            #pragma unroll
            for (int nt = 0; nt < 8; nt++)
                #pragma unroll
                for (int e = 0; e < 4; e++) acc[mt][nt][e] = 0.f;

        F_ISSUE(0, Bsrc, 0)
        #pragma unroll
        for (int s = 0; s < 8; s++) {
            if (s < 7) F_ISSUE((s + 1) & 1, Bsrc, (s + 1) * 16)
            if (s < 7) { CP_WAIT(1); } else { CP_WAIT(0); }
            __syncthreads();
            const float* Bs = Bsb[s & 1];
            int kk = s * 16;
            #pragma unroll
            for (int k8 = 0; k8 < 2; k8++) {
                int kb = k8 << 3;
                uint32_t ah[2][4], al[2][4];
                #pragma unroll
                for (int mt = 0; mt < 2; mt++) {
                    int m0 = mb + mt * 16;
                    split_tf32(Ps[(m0 + g) * 130 + kk + kb + tg],         ah[mt][0], al[mt][0]);
                    split_tf32(Ps[(m0 + g + 8) * 130 + kk + kb + tg],     ah[mt][1], al[mt][1]);
                    split_tf32(Ps[(m0 + g) * 130 + kk + kb + tg + 4],     ah[mt][2], al[mt][2]);
                    split_tf32(Ps[(m0 + g + 8) * 130 + kk + kb + tg + 4], ah[mt][3], al[mt][3]);
                }
                #pragma unroll
                for (int nt = 0; nt < 8; nt++) {
                    uint32_t bh[2], bl[2];
                    split_tf32(Bs[(kb + tg) * 136 + nb + nt * 8 + g],     bh[0], bl[0]);
                    split_tf32(Bs[(kb + tg + 4) * 136 + nb + nt * 8 + g], bh[1], bl[1]);
                    mma3(acc[0][nt], ah[0], al[0], bh, bl);
                    mma3(acc[1][nt], ah[1], al[1], bh, bl);
                }
            }
            __syncthreads();
        }

        // epilogue
        #pragma unroll
        for (int mt = 0; mt < 2; mt++) {
            int r0 = i0 + mb + mt * 16 + g, r1 = r0 + 8;
            const float* c0p = Cg + ((size_t)(b * LC + r0)) * DD;
            const float* c1p = Cg + ((size_t)(b * LC + r1)) * DD;
            float* o0 = out + ((size_t)(b * LC + r0)) * (4 * DD);
            float* o1 = out + ((size_t)(b * LC + r1)) * (4 * DD);
            #pragma unroll
            for (int nt = 0; nt < 8; nt++) {
                int d = nb + nt * 8 + 2 * tg;
                float2 c0 = *(const float2*)(c0p + d);
                float2 c1 = *(const float2*)(c1p + d);
                float* a = acc[mt][nt];
                if (pass == 0) {
                    *(float2*)(o0 + d) = c0;
                    *(float2*)(o1 + d) = c1;
                    *(float2*)(o0 + DD + d) = make_float2(a[0], a[1]);
                    *(float2*)(o1 + DD + d) = make_float2(a[2], a[3]);
                    *(float2*)(o0 + 2 * DD + d) = make_float2(c0.x * a[0], c0.y * a[1]);
                    *(float2*)(o1 + 2 * DD + d) = make_float2(c1.x * a[2], c1.y * a[3]);
                } else {
                    *(float2*)(o0 + 3 * DD + d) = make_float2(c0.x * a[0], c0.y * a[1]);
                    *(float2*)(o1 + 3 * DD + d) = make_float2(c1.x * a[2], c1.y * a[3]);
                }
            }
        }
    }
}

// ---------------- launch ----------------
extern "C" void kernel_launch(void* const* d_in, const int* in_sizes, int n_in,
                              void* d_out, int out_size) {
    const float* C     = (const float*)d_in[0];
    const float* Q     = (const float*)d_in[1];
    const int*   Cmask = (const int*)d_in[2];
    const int*   Qmask = (const int*)d_in[3];
    const float* w_c   = (const float*)d_in[4];
    const float* w_q   = (const float*)d_in[5];
    const float* w_mul = (const float*)d_in[6];
    const float* bias  = (const float*)d_in[7];
    float* out = (float*)d_out;

    cudaFuncSetAttribute(s_kernel, cudaFuncAttributeMaxDynamicSharedMemorySize, S_DYN);
    cudaFuncSetAttribute(v2_kernel, cudaFuncAttributeMaxDynamicSharedMemorySize, V2_DYN);
    cudaFuncSetAttribute(final_kernel, cudaFuncAttributeMaxDynamicSharedMemorySize, F_DYN);

    dots_kernel<<<(BB * LC + BB * LQ) / 8, 256>>>(C, Q, w_c, w_q);
    s_kernel<<<BB * 8, 256, S_DYN>>>(C, Q, w_mul, bias, Qmask, Cmask);
    colmerge_kernel<<<(BB * LQ + 255) / 256, 256>>>();
    v2_kernel<<<BB * 8, 256, V2_DYN>>>(C, Cmask);
    v2reduce_kernel<<<(BB * LQ * DD / 4 + 255) / 256, 256>>>();
    final_kernel<<<BB * 8, 256, F_DYN>>>(C, Q, Qmask, out);
}

// round 9
// speedup vs baseline: 1.8316x; 1.2267x over previous
#include <cuda_runtime.h>
#include <math.h>
#include <stdint.h>

#define BB 64
#define LC 1024
#define LQ 128
#define DD 128
#define NEG (-1e9f)

// ---------------- device scratch ----------------
__device__ float g_S[(size_t)BB * LC * LQ];      // X = exp(S), 32 MB
__device__ float g_cdot[BB * LC];
__device__ float g_qdot[BB * LQ];
__device__ float g_rinv[BB * LC];
__device__ float g_cps[BB * 8 * LQ];
__device__ float g_cinv[BB * LQ];
__device__ float g_V2p[(size_t)4 * BB * LQ * DD];
__device__ float g_V2[BB * LQ * DD];

// ---------------- helpers ----------------
__device__ __forceinline__ void split_tf32(float x, uint32_t& hi, uint32_t& lo) {
    asm("cvt.rna.tf32.f32 %0, %1;" : "=r"(hi) : "f"(x));
    float r = x - __uint_as_float(hi);
    asm("cvt.rna.tf32.f32 %0, %1;" : "=r"(lo) : "f"(r));
}
__device__ __forceinline__ uint32_t cvt_tf32(float x) {
    uint32_t h;
    asm("cvt.rna.tf32.f32 %0, %1;" : "=r"(h) : "f"(x));
    return h;
}
__device__ __forceinline__ void mma8(float* d, const uint32_t* a, const uint32_t* b) {
    asm("mma.sync.aligned.m16n8k8.row.col.f32.tf32.tf32.f32 "
        "{%0,%1,%2,%3}, {%4,%5,%6,%7}, {%8,%9}, {%0,%1,%2,%3};"
        : "+f"(d[0]), "+f"(d[1]), "+f"(d[2]), "+f"(d[3])
        : "r"(a[0]), "r"(a[1]), "r"(a[2]), "r"(a[3]), "r"(b[0]), "r"(b[1]));
}
__device__ __forceinline__ void mma3(float* d, const uint32_t* ah, const uint32_t* al,
                                     const uint32_t* bh, const uint32_t* bl) {
    mma8(d, ah, bh);
    mma8(d, ah, bl);
    mma8(d, al, bh);
}
__device__ __forceinline__ void cpa16(uint32_t dst, const float* src) {
    asm volatile("cp.async.cg.shared.global [%0], [%1], 16;" :: "r"(dst), "l"(src));
}
#define CP_COMMIT() asm volatile("cp.async.commit_group;" ::: "memory")
#define CP_WAIT(n)  asm volatile("cp.async.wait_group %0;" :: "n"(n) : "memory")

// ================= K0: row dots =================
__global__ __launch_bounds__(256) void dots_kernel(
    const float* __restrict__ Cg, const float* __restrict__ Qg,
    const float* __restrict__ w_c, const float* __restrict__ w_q) {
    int warp = (blockIdx.x * blockDim.x + threadIdx.x) >> 5;
    int lane = threadIdx.x & 31;
    if (warp < BB * LC) {
        float4 v = ((const float4*)(Cg + (size_t)warp * DD))[lane];
        float4 w = ((const float4*)w_c)[lane];
        float s = v.x * w.x + v.y * w.y + v.z * w.z + v.w * w.w;
        #pragma unroll
        for (int o = 16; o; o >>= 1) s += __shfl_xor_sync(0xffffffffu, s, o);
        if (lane == 0) g_cdot[warp] = s;
    } else {
        int r = warp - BB * LC;
        if (r < BB * LQ) {
            float4 v = ((const float4*)(Qg + (size_t)r * DD))[lane];
            float4 w = ((const float4*)w_q)[lane];
            float s = v.x * w.x + v.y * w.y + v.z * w.z + v.w * w.w;
            #pragma unroll
            for (int o = 16; o; o >>= 1) s += __shfl_xor_sync(0xffffffffu, s, o);
            if (lane == 0) g_qdot[r] = s;
        }
    }
}

// ================= K1: S GEMM (3xTF32, cp.async pipelined) ===============
#define S_DYN (4 * 128 * 36 * 4)
__global__ __launch_bounds__(256, 2) void s_kernel(
    const float* __restrict__ Cg, const float* __restrict__ Qg,
    const float* __restrict__ w_mul, const float* __restrict__ bias,
    const int* __restrict__ Qmask, const int* __restrict__ Cmask) {
    extern __shared__ float dynf[];
    float* Ab[2] = {dynf, dynf + 128 * 36};
    float* Qb2[2] = {dynf + 2 * 128 * 36, dynf + 3 * 128 * 36};
    float* Ss = dynf;                // [128][132] epilogue alias
    __shared__ float s_cd[128], s_qd[128], s_wm[128];
    __shared__ float s_s2[128];
    __shared__ int s_qm[128], s_cm[128];

    int bx = blockIdx.x;
    int b = bx >> 3, tile = bx & 7, i0 = tile << 7;
    int t = threadIdx.x, wid = t >> 5, lane = t & 31;
    int g = lane >> 2, tg = lane & 3;
    int wm_ = wid & 3, wn = wid >> 2;
    int mb = wm_ << 5;
    int jb = wn << 6;

    if (t < 128) {
        s_qm[t] = Qmask[b * LQ + t];
        s_cm[t] = Cmask[b * LC + i0 + t];
        s_wm[t] = w_mul[t];
        s_cd[t] = g_cdot[b * LC + i0 + t];
        s_qd[t] = g_qdot[b * LQ + t];
    }

    const float* Cb = Cg + ((size_t)b * LC + i0) * DD;
    const float* Qb = Qg + (size_t)b * LQ * DD;
    uint32_t aB[2], qB[2];
    aB[0] = (uint32_t)__cvta_generic_to_shared(Ab[0]);
    aB[1] = (uint32_t)__cvta_generic_to_shared(Ab[1]);
    qB[0] = (uint32_t)__cvta_generic_to_shared(Qb2[0]);
    qB[1] = (uint32_t)__cvta_generic_to_shared(Qb2[1]);

    float acc[2][8][4];
    #pragma unroll
    for (int mt = 0; mt < 2; mt++)
        #pragma unroll
        for (int nt = 0; nt < 8; nt++)
            #pragma unroll
            for (int e = 0; e < 4; e++) acc[mt][nt][e] = 0.f;

    #define S_ISSUE(buf, kk) {                                              \
        _Pragma("unroll")                                                   \
        for (int u = 0; u < 4; u++) {                                       \
            int gid = u * 256 + t, row = gid >> 3, ch = gid & 7;            \
            cpa16(aB[buf] + (row * 36 + ch * 4) * 4, Cb + (size_t)row * DD + (kk) + ch * 4); \
            cpa16(qB[buf] + (row * 36 + ch * 4) * 4, Qb + (size_t)row * DD + (kk) + ch * 4); \
        }                                                                   \
        CP_COMMIT(); }

    S_ISSUE(0, 0)
    #pragma unroll
    for (int s = 0; s < 4; s++) {
        if (s < 3) S_ISSUE((s + 1) & 1, (s + 1) * 32)
        if (s < 3) { CP_WAIT(1); } else { CP_WAIT(0); }
        __syncthreads();
        const float* As = Ab[s & 1];
        const float* Qs = Qb2[s & 1];
        int kk = s * 32;
        #pragma unroll
        for (int k8 = 0; k8 < 4; k8++) {
            int kb = k8 << 3;
            float wm0 = s_wm[kk + kb + tg], wm1 = s_wm[kk + kb + tg + 4];
            uint32_t ah[2][4], al[2][4];
            #pragma unroll
            for (int mt = 0; mt < 2; mt++) {
                int m0 = mb + mt * 16;
                split_tf32(As[(m0 + g) * 36 + kb + tg] * wm0,         ah[mt][0], al[mt][0]);
                split_tf32(As[(m0 + g + 8) * 36 + kb + tg] * wm0,     ah[mt][1], al[mt][1]);
                split_tf32(As[(m0 + g) * 36 + kb + tg + 4] * wm1,     ah[mt][2], al[mt][2]);
                split_tf32(As[(m0 + g + 8) * 36 + kb + tg + 4] * wm1, ah[mt][3], al[mt][3]);
            }
            #pragma unroll
            for (int nt = 0; nt < 8; nt++) {
                uint32_t bh[2], bl[2];
                split_tf32(Qs[(jb + nt * 8 + g) * 36 + kb + tg],     bh[0], bl[0]);
                split_tf32(Qs[(jb + nt * 8 + g) * 36 + kb + tg + 4], bh[1], bl[1]);
                mma3(acc[0][nt], ah[0], al[0], bh, bl);
                mma3(acc[1][nt], ah[1], al[1], bh, bl);
            }
        }
        __syncthreads();
    }

    // finalize S into Ss
    {
        float bi = bias[0];
        #pragma unroll
        for (int mt = 0; mt < 2; mt++) {
            int m0 = mb + mt * 16;
            float cd0 = s_cd[m0 + g] + bi, cd1 = s_cd[m0 + g + 8] + bi;
            #pragma unroll
            for (int nt = 0; nt < 8; nt++) {
                int c0 = jb + nt * 8 + 2 * tg;
                float q0 = s_qd[c0], q1 = s_qd[c0 + 1];
                Ss[(m0 + g) * 132 + c0]     = acc[mt][nt][0] + cd0 + q0;
                Ss[(m0 + g) * 132 + c0 + 1] = acc[mt][nt][1] + cd0 + q1;
                Ss[(m0 + g + 8) * 132 + c0]     = acc[mt][nt][2] + cd1 + q0;
                Ss[(m0 + g + 8) * 132 + c0 + 1] = acc[mt][nt][3] + cd1 + q1;
            }
        }
    }
    __syncthreads();

    // phase A: X = exp(S) -> Ss & g_S ; masked row sums
    {
        int i = t >> 1, j0 = (t & 1) << 6;
        float sm = 0.f;
        float* dst = g_S + ((size_t)(b * LC + i0 + i)) * LQ + j0;
        #pragma unroll
        for (int u = 0; u < 64; u += 4) {
            float4 v = *(const float4*)&Ss[i * 132 + j0 + u];
            int4 m = *(const int4*)&s_qm[j0 + u];
            float4 x = make_float4(__expf(v.x), __expf(v.y), __expf(v.z), __expf(v.w));
            *(float4*)&Ss[i * 132 + j0 + u] = x;
            *(float4*)(dst + u) = x;
            sm += (m.x ? x.x : 0.f) + (m.y ? x.y : 0.f)
                + (m.z ? x.z : 0.f) + (m.w ? x.w : 0.f);
        }
        sm += __shfl_xor_sync(0xffffffffu, sm, 1);
        if ((t & 1) == 0) g_rinv[b * LC + i0 + i] = 1.f / sm;
    }
    __syncthreads();

    // phase B: masked column partial sums
    {
        int j = t & 127, ih = t >> 7;
        float s = 0.f;
        #pragma unroll 8
        for (int r = 0; r < 64; r++) {
            int i = ih * 64 + r;
            s += s_cm[i] ? Ss[i * 132 + j] : 0.f;
        }
        if (ih == 1) s_s2[j] = s;
        __syncthreads();
        if (ih == 0)
            g_cps[(b * 8 + tile) * LQ + j] = s + s_s2[j];
    }
}

// ================= K2: merge column partial sums =================
__global__ __launch_bounds__(256) void colmerge_kernel() {
    int idx = blockIdx.x * blockDim.x + threadIdx.x;
    if (idx >= BB * LQ) return;
    int b = idx >> 7, j = idx & 127;
    float S = 0.f;
    #pragma unroll
    for (int g = 0; g < 8; g++) S += g_cps[(b * 8 + g) * LQ + j];
    g_cinv[idx] = 1.f / S;
}

// ================= K3: V2 partial (2-term tf32, cp.async), split-K=4 =====
// grid = BB*4, block 256. K=256 rows per block, 8 stages of 32.
#define V2_DYN (4 * 32 * 136 * 4)
__global__ __launch_bounds__(256, 2) void v2_kernel(
    const float* __restrict__ Cg, const int* __restrict__ Cmask) {
    extern __shared__ float dynf[];
    float* Xb[2] = {dynf, dynf + 32 * 136};
    float* Cb2[2] = {dynf + 2 * 32 * 136, dynf + 3 * 32 * 136};
    __shared__ int s_cm[256];
    int b = blockIdx.x >> 2, gc = blockIdx.x & 3;
    int t = threadIdx.x, wid = t >> 5, lane = t & 31;
    int g = lane >> 2, tg = lane & 3;
    int wm_ = wid >> 1, wn = wid & 1;
    int mb0 = wm_ << 5;
    int nb = wn << 6;
    s_cm[t] = Cmask[b * LC + gc * 256 + t];

    float ci_[2][2];
    #pragma unroll
    for (int mt = 0; mt < 2; mt++) {
        ci_[mt][0] = g_cinv[b * LQ + mb0 + mt * 16 + g];
        ci_[mt][1] = g_cinv[b * LQ + mb0 + mt * 16 + g + 8];
    }

    const float* Sb = g_S + ((size_t)(b * LC + gc * 256)) * LQ;
    const float* Cb = Cg + ((size_t)(b * LC + gc * 256)) * DD;
    uint32_t xB[2], cB[2];
    xB[0] = (uint32_t)__cvta_generic_to_shared(Xb[0]);
    xB[1] = (uint32_t)__cvta_generic_to_shared(Xb[1]);
    cB[0] = (uint32_t)__cvta_generic_to_shared(Cb2[0]);
    cB[1] = (uint32_t)__cvta_generic_to_shared(Cb2[1]);

    float acc[2][8][4];
    #pragma unroll
    for (int mt = 0; mt < 2; mt++)
        #pragma unroll
        for (int nt = 0; nt < 8; nt++)
            #pragma unroll
            for (int e = 0; e < 4; e++) acc[mt][nt][e] = 0.f;

    #define V_ISSUE(buf, ik) {                                              \
        _Pragma("unroll")                                                   \
        for (int u = 0; u < 4; u++) {                                       \
            int gid = u * 256 + t, row = gid >> 5, ch = gid & 31;           \
            cpa16(xB[buf] + (row * 136 + ch * 4) * 4, Sb + (size_t)((ik) + row) * LQ + ch * 4); \
            cpa16(cB[buf] + (row * 136 + ch * 4) * 4, Cb + (size_t)((ik) + row) * DD + ch * 4); \
        }                                                                   \
        CP_COMMIT(); }

    V_ISSUE(0, 0)
    #pragma unroll
    for (int s = 0; s < 8; s++) {
        if (s < 7) V_ISSUE((s + 1) & 1, (s + 1) * 32)
        if (s < 7) { CP_WAIT(1); } else { CP_WAIT(0); }
        __syncthreads();
        const float* Xs = Xb[s & 1];
        const float* Cs = Cb2[s & 1];
        int ik = s * 32;
        #pragma unroll
        for (int k8 = 0; k8 < 4; k8++) {
            int kb = k8 << 3;
            float f0 = s_cm[ik + kb + tg] ? 1.f : 0.f;
            float f1 = s_cm[ik + kb + tg + 4] ? 1.f : 0.f;
            uint32_t ah[2][4], al[2][4];
            #pragma unroll
            for (int mt = 0; mt < 2; mt++) {
                int m0 = mb0 + mt * 16;
                split_tf32(Xs[(kb + tg) * 136 + m0 + g] * (f0 * ci_[mt][0]),         ah[mt][0], al[mt][0]);
                split_tf32(Xs[(kb + tg) * 136 + m0 + g + 8] * (f0 * ci_[mt][1]),     ah[mt][1], al[mt][1]);
                split_tf32(Xs[(kb + tg + 4) * 136 + m0 + g] * (f1 * ci_[mt][0]),     ah[mt][2], al[mt][2]);
                split_tf32(Xs[(kb + tg + 4) * 136 + m0 + g + 8] * (f1 * ci_[mt][1]), ah[mt][3], al[mt][3]);
            }
            #pragma unroll
            for (int nt = 0; nt < 8; nt++) {
                uint32_t bh[2];
                bh[0] = cvt_tf32(Cs[(kb + tg) * 136 + nb + nt * 8 + g]);
                bh[1] = cvt_tf32(Cs[(kb + tg + 4) * 136 + nb + nt * 8 + g]);
                mma8(acc[0][nt], ah[0], bh);
                mma8(acc[0][nt], al[0], bh);
                mma8(acc[1][nt], ah[1], bh);
                mma8(acc[1][nt], al[1], bh);
            }
        }
        __syncthreads();
    }

    float* Vp = g_V2p + (size_t)(b * 4 + gc) * LQ * DD;
    #pragma unroll
    for (int mt = 0; mt < 2; mt++) {
        int r0 = mb0 + mt * 16 + g;
        #pragma unroll
        for (int nt = 0; nt < 8; nt++) {
            int d = nb + nt * 8 + 2 * tg;
            *(float2*)(Vp + (size_t)r0 * DD + d)       = make_float2(acc[mt][nt][0], acc[mt][nt][1]);
            *(float2*)(Vp + (size_t)(r0 + 8) * DD + d) = make_float2(acc[mt][nt][2], acc[mt][nt][3]);
        }
    }
}

__global__ __launch_bounds__(256) void v2reduce_kernel() {
    int vec = blockIdx.x * blockDim.x + threadIdx.x;
    const int per_b = LQ * DD / 4;
    if (vec >= BB * per_b) return;
    int b = vec / per_b;
    int off = vec % per_b;
    float4 s = make_float4(0.f, 0.f, 0.f, 0.f);
    #pragma unroll
    for (int g = 0; g < 4; g++) {
        float4 v = ((const float4*)(g_V2p + (size_t)(b * 4 + g) * LQ * DD))[off];
        s.x += v.x; s.y += v.y; s.z += v.z; s.w += v.w;
    }
    ((float4*)g_V2)[vec] = s;
}

// ================= K4: A = P1@Q, Bm = P1@V2 (2-term tf32, cp.async Bs) ===
#define F_DYN ((128 * 130 + 2 * 16 * 136) * 4)
__global__ __launch_bounds__(256, 2) void final_kernel(
    const float* __restrict__ Cg, const float* __restrict__ Qg,
    const int* __restrict__ Qmask, float* __restrict__ out) {
    extern __shared__ float dynf[];
    float* Ps = dynf;                 // [128][130]
    float* Bsb[2] = {dynf + 128 * 130, dynf + 128 * 130 + 16 * 136};
    int bx = blockIdx.x;
    int b = bx >> 3, i0 = (bx & 7) << 7;
    int t = threadIdx.x, wid = t >> 5, lane = t & 31;
    int g = lane >> 2, tg = lane & 3;
    int wm_ = wid & 3, wn = wid >> 2;
    int mb = wm_ << 5, nb = wn << 6;
    uint32_t bB[2];
    bB[0] = (uint32_t)__cvta_generic_to_shared(Bsb[0]);
    bB[1] = (uint32_t)__cvta_generic_to_shared(Bsb[1]);

    {   // build P1 tile (no exp)
        int i = t >> 1, j0 = (t & 1) << 6;
        int gi = b * LC + i0 + i;
        float ri = __ldg(&g_rinv[gi]);
        const float* srow = g_S + (size_t)gi * LQ + j0;
        const int* qm = Qmask + b * LQ + j0;
        float* pr = Ps + i * 130 + j0;
        #pragma unroll
        for (int u = 0; u < 64; u += 4) {
            float4 v = *(const float4*)(srow + u);
            int4 m = *(const int4*)(qm + u);
            pr[u]     = m.x ? v.x * ri : 0.f;
            pr[u + 1] = m.y ? v.y * ri : 0.f;
            pr[u + 2] = m.z ? v.z * ri : 0.f;
            pr[u + 3] = m.w ? v.w * ri : 0.f;
        }
    }
    __syncthreads();

    #define F_ISSUE(buf, src, kk) {                                         \
        _Pragma("unroll")                                                   \
        for (int u = 0; u < 2; u++) {                                       \
            int gid = u * 256 + t, row = gid >> 5, ch = gid & 31;           \
            cpa16(bB[buf] + (row * 136 + ch * 4) * 4, (src) + (size_t)((kk) + row) * DD + ch * 4); \
        }                                                                   \
        CP_COMMIT(); }

    #pragma unroll
    for (int pass = 0; pass < 2; pass++) {
        const float* Bsrc = pass ? (g_V2 + (size_t)b * LQ * DD) : (Qg + (size_t)b * LQ * DD);
        float acc[2][8][4];
        #pragma unroll
        for (int mt = 0; mt < 2; mt++)
            #pragma unroll
            for (int nt = 0; nt < 8; nt++)
                #pragma unroll
                for (int e = 0; e < 4; e++) acc[mt][nt][e] = 0.f;

        F_ISSUE(0, Bsrc, 0)
        #pragma unroll
        for (int s = 0; s < 8; s++) {
            if (s < 7) F_ISSUE((s + 1) & 1, Bsrc, (s + 1) * 16)
            if (s < 7) { CP_WAIT(1); } else { CP_WAIT(0); }
            __syncthreads();
            const float* Bs = Bsb[s & 1];
            int kk = s * 16;
            #pragma unroll
            for (int k8 = 0; k8 < 2; k8++) {
                int kb = k8 << 3;
                uint32_t ah[2][4], al[2][4];
                #pragma unroll
                for (int mt = 0; mt < 2; mt++) {
                    int m0 = mb + mt * 16;
                    split_tf32(Ps[(m0 + g) * 130 + kk + kb + tg],         ah[mt][0], al[mt][0]);
                    split_tf32(Ps[(m0 + g + 8) * 130 + kk + kb + tg],     ah[mt][1], al[mt][1]);
                    split_tf32(Ps[(m0 + g) * 130 + kk + kb + tg + 4],     ah[mt][2], al[mt][2]);
                    split_tf32(Ps[(m0 + g + 8) * 130 + kk + kb + tg + 4], ah[mt][3], al[mt][3]);
                }
                #pragma unroll
                for (int nt = 0; nt < 8; nt++) {
                    uint32_t bh[2];
                    bh[0] = cvt_tf32(Bs[(kb + tg) * 136 + nb + nt * 8 + g]);
                    bh[1] = cvt_tf32(Bs[(kb + tg + 4) * 136 + nb + nt * 8 + g]);
                    mma8(acc[0][nt], ah[0], bh);
                    mma8(acc[0][nt], al[0], bh);
                    mma8(acc[1][nt], ah[1], bh);
                    mma8(acc[1][nt], al[1], bh);
                }
            }
            __syncthreads();
        }

        // epilogue
        #pragma unroll
        for (int mt = 0; mt < 2; mt++) {
            int r0 = i0 + mb + mt * 16 + g, r1 = r0 + 8;
            const float* c0p = Cg + ((size_t)(b * LC + r0)) * DD;
            const float* c1p = Cg + ((size_t)(b * LC + r1)) * DD;
            float* o0 = out + ((size_t)(b * LC + r0)) * (4 * DD);
            float* o1 = out + ((size_t)(b * LC + r1)) * (4 * DD);
            #pragma unroll
            for (int nt = 0; nt < 8; nt++) {
                int d = nb + nt * 8 + 2 * tg;
                float2 c0 = *(const float2*)(c0p + d);
                float2 c1 = *(const float2*)(c1p + d);
                float* a = acc[mt][nt];
                if (pass == 0) {
                    *(float2*)(o0 + d) = c0;
                    *(float2*)(o1 + d) = c1;
                    *(float2*)(o0 + DD + d) = make_float2(a[0], a[1]);
                    *(float2*)(o1 + DD + d) = make_float2(a[2], a[3]);
                    *(float2*)(o0 + 2 * DD + d) = make_float2(c0.x * a[0], c0.y * a[1]);
                    *(float2*)(o1 + 2 * DD + d) = make_float2(c1.x * a[2], c1.y * a[3]);
                } else {
                    *(float2*)(o0 + 3 * DD + d) = make_float2(c0.x * a[0], c0.y * a[1]);
                    *(float2*)(o1 + 3 * DD + d) = make_float2(c1.x * a[2], c1.y * a[3]);
                }
            }
        }
    }
}

// ---------------- launch ----------------
extern "C" void kernel_launch(void* const* d_in, const int* in_sizes, int n_in,
                              void* d_out, int out_size) {
    const float* C     = (const float*)d_in[0];
    const float* Q     = (const float*)d_in[1];
    const int*   Cmask = (const int*)d_in[2];
    const int*   Qmask = (const int*)d_in[3];
    const float* w_c   = (const float*)d_in[4];
    const float* w_q   = (const float*)d_in[5];
    const float* w_mul = (const float*)d_in[6];
    const float* bias  = (const float*)d_in[7];
    float* out = (float*)d_out;

    cudaFuncSetAttribute(s_kernel, cudaFuncAttributeMaxDynamicSharedMemorySize, S_DYN);
    cudaFuncSetAttribute(v2_kernel, cudaFuncAttributeMaxDynamicSharedMemorySize, V2_DYN);
    cudaFuncSetAttribute(final_kernel, cudaFuncAttributeMaxDynamicSharedMemorySize, F_DYN);

    dots_kernel<<<(BB * LC + BB * LQ) / 8, 256>>>(C, Q, w_c, w_q);
    s_kernel<<<BB * 8, 256, S_DYN>>>(C, Q, w_mul, bias, Qmask, Cmask);
    colmerge_kernel<<<(BB * LQ + 255) / 256, 256>>>();
    v2_kernel<<<BB * 4, 256, V2_DYN>>>(C, Cmask);
    v2reduce_kernel<<<(BB * LQ * DD / 4 + 255) / 256, 256>>>();
    final_kernel<<<BB * 8, 256, F_DYN>>>(C, Q, Qmask, out);
}